// round 1
// baseline (speedup 1.0000x reference)
#include <cuda_runtime.h>
#include <cstdint>

// ---------------------------------------------------------------------------
// Problem constants
// ---------------------------------------------------------------------------
#define NF   768
#define NB1  512          // batch for graph pass 1 (N*FR)
#define NN1  50           // nodes graph 1
#define NB2  16           // batch graph 2
#define NN2  32           // nodes graph 2
#define M1   (NB1*NN1)    // 25600 rows
#define M2   (NB2*NN2)    // 512 rows
#define NC   400
#define NF2  (2*NF)

// ---------------------------------------------------------------------------
// Scratch (device globals; no runtime allocation allowed)
// ---------------------------------------------------------------------------
__device__ float g_qx  [(size_t)M1 * NF];
__device__ float g_kx  [(size_t)M1 * NF];
__device__ float g_xw  [(size_t)M1 * NF];
__device__ float g_h   [(size_t)M1 * NF];
__device__ float g_x   [(size_t)M1 * NF];
__device__ float g_adj [(size_t)NB1 * NN1 * NN1];
__device__ float g_mean[(size_t)NB1 * NF];   // graph1 output == graph2 input
__device__ float g_mean2[(size_t)NB2 * NF];  // graph2 output
__device__ float g_hc  [(size_t)NB2 * NF];   // classifier hidden

// ---------------------------------------------------------------------------
// SGEMM: C[M,N] = A[M,K] * op(B) + bias, optional ReLU
//   BT=true : B row-major [N,K]  (C = A @ B^T)
//   BT=false: B row-major [K,N]  (C = A @ B)
// 128x128x16 tile, 256 threads, 8x8 per-thread register tile.
// ---------------------------------------------------------------------------
template<bool BT, bool RELU>
__global__ __launch_bounds__(256, 2)
void sgemm_kernel(const float* __restrict__ A, const float* __restrict__ B,
                  const float* __restrict__ bias, float* __restrict__ C,
                  int M, int N, int K)
{
    constexpr int BM = 128, BN = 128, BK = 16, TM = 8, TN = 8;
    __shared__ __align__(16) float As[BK][BM];
    __shared__ __align__(16) float Bs[BK][BN];

    const int tid = threadIdx.x;
    const int tx  = tid & 15;        // 0..15
    const int ty  = tid >> 4;        // 0..15
    const int row0 = blockIdx.y * BM;
    const int col0 = blockIdx.x * BN;

    float acc[TM][TN];
    #pragma unroll
    for (int i = 0; i < TM; i++)
        #pragma unroll
        for (int j = 0; j < TN; j++) acc[i][j] = 0.f;

    for (int k0 = 0; k0 < K; k0 += BK) {
        // load A tile: BM*BK = 2048 elems, 8 per thread
        #pragma unroll
        for (int i = 0; i < 8; i++) {
            int idx = tid + i * 256;
            int m = idx >> 4, k = idx & 15;
            int gm = row0 + m;
            As[k][m] = (gm < M) ? A[(size_t)gm * K + k0 + k] : 0.f;
        }
        // load B tile
        #pragma unroll
        for (int i = 0; i < 8; i++) {
            int idx = tid + i * 256;
            if (BT) {
                int n = idx >> 4, k = idx & 15;
                int gn = col0 + n;
                Bs[k][n] = (gn < N) ? B[(size_t)gn * K + k0 + k] : 0.f;
            } else {
                int k = idx >> 7, n = idx & 127;
                int gn = col0 + n;
                Bs[k][n] = (gn < N) ? B[(size_t)(k0 + k) * N + gn] : 0.f;
            }
        }
        __syncthreads();

        #pragma unroll
        for (int kk = 0; kk < BK; kk++) {
            float a[TM], b[TN];
            const float4* ap = reinterpret_cast<const float4*>(&As[kk][ty * TM]);
            const float4* bp = reinterpret_cast<const float4*>(&Bs[kk][tx * TN]);
            reinterpret_cast<float4*>(a)[0] = ap[0];
            reinterpret_cast<float4*>(a)[1] = ap[1];
            reinterpret_cast<float4*>(b)[0] = bp[0];
            reinterpret_cast<float4*>(b)[1] = bp[1];
            #pragma unroll
            for (int i = 0; i < TM; i++)
                #pragma unroll
                for (int j = 0; j < TN; j++)
                    acc[i][j] += a[i] * b[j];
        }
        __syncthreads();
    }

    #pragma unroll
    for (int i = 0; i < TM; i++) {
        int gm = row0 + ty * TM + i;
        if (gm >= M) continue;
        #pragma unroll
        for (int j = 0; j < TN; j++) {
            int gn = col0 + tx * TN + j;
            if (gn < N) {
                float v = acc[i][j] + (bias ? bias[gn] : 0.f);
                if (RELU) v = fmaxf(v, 0.f);
                C[(size_t)gm * N + gn] = v;
            }
        }
    }
}

// ---------------------------------------------------------------------------
// Adjacency: per batch b, dot[n,m] = <qx[b,n,:], kx[b,m,:]>, sq = dot^2,
// adj = sq / max(rowsum(sq), 1e-12). One block per batch, 256 threads.
// ---------------------------------------------------------------------------
template<int NN>
__global__ void adj_kernel(const float* __restrict__ QX, const float* __restrict__ KX,
                           float* __restrict__ ADJ, int d)
{
    constexpr int NP  = NN * NN;
    constexpr int PPT = (NP + 255) / 256;
    constexpr int DK  = 32;
    __shared__ float qs[NN][DK + 1];
    __shared__ float ks[NN][DK + 1];
    __shared__ float rowsum[NN];

    const int b = blockIdx.x, tid = threadIdx.x;
    const float* q = QX + (size_t)b * NN * d;
    const float* k = KX + (size_t)b * NN * d;

    float acc[PPT];
    #pragma unroll
    for (int p = 0; p < PPT; p++) acc[p] = 0.f;

    for (int k0 = 0; k0 < d; k0 += DK) {
        __syncthreads();
        for (int idx = tid; idx < NN * DK; idx += 256) {
            int n = idx / DK, kk = idx % DK;
            qs[n][kk] = q[(size_t)n * d + k0 + kk];
            ks[n][kk] = k[(size_t)n * d + k0 + kk];
        }
        __syncthreads();
        #pragma unroll
        for (int p = 0; p < PPT; p++) {
            int pair = tid + p * 256;
            if (pair < NP) {
                int n = pair / NN, m = pair % NN;
                float a = acc[p];
                #pragma unroll
                for (int kk = 0; kk < DK; kk++) a += qs[n][kk] * ks[m][kk];
                acc[p] = a;
            }
        }
    }

    if (tid < NN) rowsum[tid] = 0.f;
    __syncthreads();
    float sq[PPT];
    #pragma unroll
    for (int p = 0; p < PPT; p++) {
        int pair = tid + p * 256;
        if (pair < NP) {
            sq[p] = acc[p] * acc[p];
            atomicAdd(&rowsum[pair / NN], sq[p]);
        }
    }
    __syncthreads();
    #pragma unroll
    for (int p = 0; p < PPT; p++) {
        int pair = tid + p * 256;
        if (pair < NP)
            ADJ[(size_t)b * NP + pair] = sq[p] / fmaxf(rowsum[pair / NN], 1e-12f);
    }
}

// ---------------------------------------------------------------------------
// h[b,n,:] = sum_m adj[b,n,m] * xw[b,m,:]. One block per batch.
// adj staged in smem; xw streamed in 128-column chunks.
// ---------------------------------------------------------------------------
template<int NN>
__global__ void adjmm_kernel(const float* __restrict__ ADJ, const float* __restrict__ XW,
                             float* __restrict__ H, int d)
{
    constexpr int CJ  = 128;
    constexpr int RG  = 256 / CJ;              // 2 row-groups
    constexpr int NPT = (NN + RG - 1) / RG;    // rows per thread
    __shared__ float adjs[NN * NN];
    __shared__ float xws[NN][CJ];

    const int b = blockIdx.x, tid = threadIdx.x;
    const int j = tid & (CJ - 1);
    const int r = tid >> 7;

    for (int idx = tid; idx < NN * NN; idx += 256)
        adjs[idx] = ADJ[(size_t)b * NN * NN + idx];

    const float* xw = XW + (size_t)b * NN * d;
    float*       h  = H  + (size_t)b * NN * d;

    for (int jc = 0; jc < d; jc += CJ) {
        __syncthreads();
        for (int idx = tid; idx < NN * CJ; idx += 256) {
            int m = idx / CJ, jj = idx % CJ;
            xws[m][jj] = xw[(size_t)m * d + jc + jj];
        }
        __syncthreads();

        float acc[NPT];
        #pragma unroll
        for (int i = 0; i < NPT; i++) acc[i] = 0.f;
        #pragma unroll
        for (int m = 0; m < NN; m++) {
            float v = xws[m][j];
            #pragma unroll
            for (int i = 0; i < NPT; i++)
                acc[i] += adjs[(r + i * RG) * NN + m] * v;
        }
        #pragma unroll
        for (int i = 0; i < NPT; i++) {
            int n = r + i * RG;
            if (n < NN) h[(size_t)n * d + jc + j] = acc[i];
        }
    }
}

// ---------------------------------------------------------------------------
// x = relu(LayerNorm(h) * g + b), one block per row, 256 threads, d=768
// ---------------------------------------------------------------------------
__global__ void ln_relu_kernel(const float* __restrict__ H, const float* __restrict__ g,
                               const float* __restrict__ bb, float* __restrict__ O, int d)
{
    const int row = blockIdx.x;
    const float* h = H + (size_t)row * d;
    float s = 0.f, ss = 0.f;
    float vals[3];
    int cnt = 0;
    for (int jj = threadIdx.x; jj < d; jj += 256) {
        float v = h[jj];
        vals[cnt++] = v;
        s += v; ss += v * v;
    }
    #pragma unroll
    for (int o = 16; o; o >>= 1) {
        s  += __shfl_xor_sync(0xffffffffu, s, o);
        ss += __shfl_xor_sync(0xffffffffu, ss, o);
    }
    __shared__ float reds[8], redss[8], smu[1], srs[1];
    int w = threadIdx.x >> 5, l = threadIdx.x & 31;
    if (l == 0) { reds[w] = s; redss[w] = ss; }
    __syncthreads();
    if (threadIdx.x == 0) {
        float ts = 0.f, tss = 0.f;
        #pragma unroll
        for (int i = 0; i < 8; i++) { ts += reds[i]; tss += redss[i]; }
        float mu  = ts / d;
        float var = tss / d - mu * mu;
        smu[0] = mu;
        srs[0] = rsqrtf(var + 1e-5f);
    }
    __syncthreads();
    float mu = smu[0], rs = srs[0];
    cnt = 0;
    for (int jj = threadIdx.x; jj < d; jj += 256) {
        float v = (vals[cnt++] - mu) * rs * g[jj] + bb[jj];
        O[(size_t)row * d + jj] = fmaxf(v, 0.f);
    }
}

// ---------------------------------------------------------------------------
// Mean over nodes: out[b,j] = (1/NN) sum_n x[b,n,j]
// ---------------------------------------------------------------------------
template<int NN>
__global__ void mean_kernel(const float* __restrict__ X, float* __restrict__ O, int d)
{
    const int b = blockIdx.x;
    for (int jj = threadIdx.x; jj < d; jj += 256) {
        float s = 0.f;
        #pragma unroll 10
        for (int i = 0; i < NN; i++)
            s += X[((size_t)b * NN + i) * d + jj];
        O[(size_t)b * d + jj] = s * (1.f / NN);
    }
}

// y[i] = concat(a[i], g2[i]) per row
__global__ void concat_kernel(const float* __restrict__ a, const float* __restrict__ g2,
                              float* __restrict__ y, int d)
{
    const int i = blockIdx.x;
    for (int jj = threadIdx.x; jj < d; jj += 256) {
        y[(size_t)i * 2 * d + jj]     = a[(size_t)i * d + jj];
        y[(size_t)i * 2 * d + d + jj] = g2[(size_t)i * d + jj];
    }
}

// ---------------------------------------------------------------------------
// Host side
// ---------------------------------------------------------------------------
static inline dim3 gemm_grid(int M, int N) {
    return dim3((N + 127) / 128, (M + 127) / 128);
}

// run one _graph pass: x_in [Bt, nn, NF] -> out_mean [Bt, NF]
template<int NN>
static void run_graph(const float* x_in, int Bt,
                      const float* wq_w, const float* wq_b,
                      const float* wk_w, const float* wk_b,
                      const float* gcn_w, const float* ln_g, const float* ln_b,
                      float* p_qx, float* p_kx, float* p_xw, float* p_h,
                      float* p_x, float* p_adj, float* out_mean)
{
    const int M = Bt * NN;
    // projections
    sgemm_kernel<true, false><<<gemm_grid(M, NF), 256>>>(x_in, wq_w, wq_b, p_qx, M, NF, NF);
    sgemm_kernel<true, false><<<gemm_grid(M, NF), 256>>>(x_in, wk_w, wk_b, p_kx, M, NF, NF);
    // adjacency
    adj_kernel<NN><<<Bt, 256>>>(p_qx, p_kx, p_adj, NF);
    // layer 0
    sgemm_kernel<false, false><<<gemm_grid(M, NF), 256>>>(x_in, gcn_w, nullptr, p_xw, M, NF, NF);
    adjmm_kernel<NN><<<Bt, 256>>>(p_adj, p_xw, p_h, NF);
    ln_relu_kernel<<<M, 256>>>(p_h, ln_g, ln_b, p_x, NF);
    // layer 1
    sgemm_kernel<false, false><<<gemm_grid(M, NF), 256>>>(p_x, gcn_w + (size_t)NF * NF, nullptr, p_xw, M, NF, NF);
    adjmm_kernel<NN><<<Bt, 256>>>(p_adj, p_xw, p_h, NF);
    ln_relu_kernel<<<M, 256>>>(p_h, ln_g + NF, ln_b + NF, p_x, NF);
    // mean over nodes
    mean_kernel<NN><<<Bt, 256>>>(p_x, out_mean, NF);
}

extern "C" void kernel_launch(void* const* d_in, const int* in_sizes, int n_in,
                              void* d_out, int out_size)
{
    const float* feats  = (const float*)d_in[0];   // [16,32,50,768]
    const float* fglob  = (const float*)d_in[1];   // [16,768]
    // d_in[2] = feat_single_previous (unused)
    const float* wq_w   = (const float*)d_in[3];
    const float* wq_b   = (const float*)d_in[4];
    const float* wk_w   = (const float*)d_in[5];
    const float* wk_b   = (const float*)d_in[6];
    const float* gcn_w  = (const float*)d_in[7];   // [2,768,768]
    const float* ln_g   = (const float*)d_in[8];   // [2,768]
    const float* ln_b   = (const float*)d_in[9];
    const float* fc1_w  = (const float*)d_in[10];  // [768,1536]
    const float* fc1_b  = (const float*)d_in[11];
    const float* fc2_w  = (const float*)d_in[12];  // [400,768]
    const float* fc2_b  = (const float*)d_in[13];
    float* out = (float*)d_out;                    // logits[16*400] then y[16*1536]

    float *p_qx, *p_kx, *p_xw, *p_h, *p_x, *p_adj, *p_mean, *p_mean2, *p_hc;
    cudaGetSymbolAddress((void**)&p_qx,   g_qx);
    cudaGetSymbolAddress((void**)&p_kx,   g_kx);
    cudaGetSymbolAddress((void**)&p_xw,   g_xw);
    cudaGetSymbolAddress((void**)&p_h,    g_h);
    cudaGetSymbolAddress((void**)&p_x,    g_x);
    cudaGetSymbolAddress((void**)&p_adj,  g_adj);
    cudaGetSymbolAddress((void**)&p_mean, g_mean);
    cudaGetSymbolAddress((void**)&p_mean2,g_mean2);
    cudaGetSymbolAddress((void**)&p_hc,   g_hc);

    // ---- graph pass 1: [512, 50, 768] -> [512, 768] ----
    run_graph<NN1>(feats, NB1, wq_w, wq_b, wk_w, wk_b, gcn_w, ln_g, ln_b,
                   p_qx, p_kx, p_xw, p_h, p_x, p_adj, p_mean);

    // ---- graph pass 2: [16, 32, 768] -> [16, 768] ----
    run_graph<NN2>(p_mean, NB2, wq_w, wq_b, wk_w, wk_b, gcn_w, ln_g, ln_b,
                   p_qx, p_kx, p_xw, p_h, p_x, p_adj, p_mean2);

    // ---- classifier ----
    float* y_out = out + NB2 * NC;   // y region: [16, 1536]
    concat_kernel<<<NB2, 256>>>(p_mean2, fglob, y_out, NF);
    // h = relu(y @ fc1_w^T + fc1_b)  : [16,1536] x [768,1536]^T
    sgemm_kernel<true, true ><<<gemm_grid(NB2, NF), 256>>>(y_out, fc1_w, fc1_b, p_hc, NB2, NF, NF2);
    // logits = h @ fc2_w^T + fc2_b   : [16,768] x [400,768]^T
    sgemm_kernel<true, false><<<gemm_grid(NB2, NC), 256>>>(p_hc, fc2_w, fc2_b, out, NB2, NC, NF);
}

// round 2
// speedup vs baseline: 2.2783x; 2.2783x over previous
#include <cuda_runtime.h>
#include <cstdint>

// ---------------------------------------------------------------------------
// Problem constants
// ---------------------------------------------------------------------------
#define NF   768
#define NB1  512          // batch for graph pass 1 (N*FR)
#define NN1  50           // nodes graph 1
#define NB2  16           // batch graph 2
#define NN2  32           // nodes graph 2
#define M1   (NB1*NN1)    // 25600 rows
#define NC   400
#define NF2  (2*NF)

// ---------------------------------------------------------------------------
// Scratch (device globals; no runtime allocation allowed)
// ---------------------------------------------------------------------------
__device__ float g_qx  [(size_t)M1 * NF];
__device__ float g_kx  [(size_t)M1 * NF];
__device__ float g_xw  [(size_t)M1 * NF];
__device__ float g_h   [(size_t)M1 * NF];
__device__ float g_x   [(size_t)M1 * NF];
__device__ float g_adj [(size_t)NB1 * NN1 * NN1];
__device__ float g_mean[(size_t)NB1 * NF];
__device__ float g_mean2[(size_t)NB2 * NF];
__device__ float g_hc  [(size_t)NB2 * NF];
// transposed weights ([K][N] layouts for the GEMM)
__device__ float g_wqT [(size_t)NF * NF];
__device__ float g_wkT [(size_t)NF * NF];
__device__ float g_fc1T[(size_t)NF2 * NF];
__device__ float g_fc2T[(size_t)NF * NC];

// ---------------------------------------------------------------------------
// tf32 helpers
// ---------------------------------------------------------------------------
__device__ __forceinline__ uint32_t f2tf32(float f) {
    uint32_t r;
    asm("cvt.rna.tf32.f32 %0, %1;" : "=r"(r) : "f"(f));
    return r;
}

__device__ __forceinline__ void mma_tf32(float* d, const uint32_t* a, const uint32_t* b) {
    asm volatile(
        "mma.sync.aligned.m16n8k8.row.col.f32.tf32.tf32.f32 "
        "{%0,%1,%2,%3}, {%4,%5,%6,%7}, {%8,%9}, {%0,%1,%2,%3};"
        : "+f"(d[0]), "+f"(d[1]), "+f"(d[2]), "+f"(d[3])
        : "r"(a[0]), "r"(a[1]), "r"(a[2]), "r"(a[3]), "r"(b[0]), "r"(b[1]));
}

// ---------------------------------------------------------------------------
// TF32 GEMM: C[M,N] = A[M,K] @ B[K,N] + bias, optional ReLU.
// 128x128x32 block tile, 256 threads (8 warps of 64x32), m16n8k8 tf32 mma.
// K must be a multiple of 32 (true for all call sites: 768 / 1536).
// ---------------------------------------------------------------------------
template<bool RELU>
__global__ __launch_bounds__(256, 2)
void gemm_tf32(const float* __restrict__ A, const float* __restrict__ B,
               const float* __restrict__ bias, float* __restrict__ C,
               int M, int N, int K)
{
    constexpr int BM = 128, BN = 128, BK = 32;
    constexpr int AKP = 40;    // A smem row stride (floats) — conflict-free frag loads
    constexpr int BNP = 132;   // B smem row stride

    __shared__ uint32_t As[BM * AKP];   // 20480 B
    __shared__ uint32_t Bs[BK * BNP];   // 16896 B

    const int tid  = threadIdx.x;
    const int wid  = tid >> 5;
    const int lane = tid & 31;
    const int gid  = lane >> 2;       // 0..7
    const int cq   = lane & 3;        // 0..3
    const int wm   = (wid >> 2) * 64; // warp row offset within block (0/64)
    const int wn   = (wid & 3) * 32;  // warp col offset (0/32/64/96)

    const int row0 = blockIdx.y * BM;
    const int col0 = blockIdx.x * BN;

    float acc[4][4][4];
    #pragma unroll
    for (int i = 0; i < 4; i++)
        #pragma unroll
        for (int j = 0; j < 4; j++)
            #pragma unroll
            for (int q = 0; q < 4; q++) acc[i][j][q] = 0.f;

    for (int k0 = 0; k0 < K; k0 += BK) {
        // ---- stage A tile: BM x BK, tf32-converted, k-permuted within 8 ----
        #pragma unroll
        for (int i = 0; i < 4; i++) {
            int u  = tid + i * 256;          // 0..1023 float4 slots
            int m  = u >> 3;                  // 8 float4 per row
            int kq = u & 7;
            int gm = row0 + m;
            float4 v = make_float4(0.f, 0.f, 0.f, 0.f);
            if (gm < M) v = *reinterpret_cast<const float4*>(A + (size_t)gm * K + k0 + 4 * kq);
            // kp(4kq + j) = 8*(kq>>1) + 2*j + (kq&1)
            int base = m * AKP + 8 * (kq >> 1) + (kq & 1);
            As[base + 0] = f2tf32(v.x);
            As[base + 2] = f2tf32(v.y);
            As[base + 4] = f2tf32(v.z);
            As[base + 6] = f2tf32(v.w);
        }
        // ---- stage B tile: BK x BN (k-major, coalesced) ----
        #pragma unroll
        for (int i = 0; i < 4; i++) {
            int u  = tid + i * 256;
            int k  = u >> 5;                  // 32 float4 per row
            int nq = u & 31;
            int gn = col0 + 4 * nq;
            const float* bp = B + (size_t)(k0 + k) * N + gn;
            float x0 = (gn + 0 < N) ? bp[0] : 0.f;
            float x1 = (gn + 1 < N) ? bp[1] : 0.f;
            float x2 = (gn + 2 < N) ? bp[2] : 0.f;
            float x3 = (gn + 3 < N) ? bp[3] : 0.f;
            int base = k * BNP + 4 * nq;
            Bs[base + 0] = f2tf32(x0);
            Bs[base + 1] = f2tf32(x1);
            Bs[base + 2] = f2tf32(x2);
            Bs[base + 3] = f2tf32(x3);
        }
        __syncthreads();

        #pragma unroll
        for (int s = 0; s < 4; s++) {       // 4 k-steps of 8
            uint32_t af[4][4];
            #pragma unroll
            for (int mt = 0; mt < 4; mt++) {
                int r0 = wm + mt * 16 + gid;
                const uint32_t* p0 = &As[(r0    ) * AKP + 8 * s + 2 * cq];
                const uint32_t* p1 = &As[(r0 + 8) * AKP + 8 * s + 2 * cq];
                uint2 t0 = *reinterpret_cast<const uint2*>(p0);
                uint2 t1 = *reinterpret_cast<const uint2*>(p1);
                af[mt][0] = t0.x; af[mt][1] = t1.x; af[mt][2] = t0.y; af[mt][3] = t1.y;
            }
            uint32_t bf[4][2];
            #pragma unroll
            for (int nt = 0; nt < 4; nt++) {
                int cn = wn + nt * 8 + gid;
                bf[nt][0] = Bs[(8 * s + cq    ) * BNP + cn];
                bf[nt][1] = Bs[(8 * s + cq + 4) * BNP + cn];
            }
            #pragma unroll
            for (int mt = 0; mt < 4; mt++)
                #pragma unroll
                for (int nt = 0; nt < 4; nt++)
                    mma_tf32(acc[mt][nt], af[mt], bf[nt]);
        }
        __syncthreads();
    }

    // ---- epilogue ----
    #pragma unroll
    for (int mt = 0; mt < 4; mt++) {
        int rlo = row0 + wm + mt * 16 + gid;
        int rhi = rlo + 8;
        #pragma unroll
        for (int nt = 0; nt < 4; nt++) {
            int cc = col0 + wn + nt * 8 + 2 * cq;
            float b0 = 0.f, b1 = 0.f;
            if (bias) {
                if (cc     < N) b0 = bias[cc];
                if (cc + 1 < N) b1 = bias[cc + 1];
            }
            float v;
            if (rlo < M) {
                if (cc < N) {
                    v = acc[mt][nt][0] + b0; if (RELU) v = fmaxf(v, 0.f);
                    C[(size_t)rlo * N + cc] = v;
                }
                if (cc + 1 < N) {
                    v = acc[mt][nt][1] + b1; if (RELU) v = fmaxf(v, 0.f);
                    C[(size_t)rlo * N + cc + 1] = v;
                }
            }
            if (rhi < M) {
                if (cc < N) {
                    v = acc[mt][nt][2] + b0; if (RELU) v = fmaxf(v, 0.f);
                    C[(size_t)rhi * N + cc] = v;
                }
                if (cc + 1 < N) {
                    v = acc[mt][nt][3] + b1; if (RELU) v = fmaxf(v, 0.f);
                    C[(size_t)rhi * N + cc + 1] = v;
                }
            }
        }
    }
}

// ---------------------------------------------------------------------------
// Transpose: out[C][R] = in[R][C]^T   (32x32 tiles, block 32x8)
// ---------------------------------------------------------------------------
__global__ void transpose_kernel(const float* __restrict__ in, float* __restrict__ out,
                                 int R, int C)
{
    __shared__ float t[32][33];
    int bx = blockIdx.x * 32, by = blockIdx.y * 32;
    int x = bx + threadIdx.x;
    for (int i = threadIdx.y; i < 32; i += 8) {
        int y = by + i;
        t[i][threadIdx.x] = (y < R && x < C) ? in[(size_t)y * C + x] : 0.f;
    }
    __syncthreads();
    int ox = by + threadIdx.x;   // out col = in row
    for (int i = threadIdx.y; i < 32; i += 8) {
        int oy = bx + i;         // out row = in col
        if (oy < C && ox < R) out[(size_t)oy * R + ox] = t[threadIdx.x][i];
    }
}

// ---------------------------------------------------------------------------
// Adjacency: per batch b, dot[n,m] = <qx[b,n,:], kx[b,m,:]>, sq = dot^2,
// adj = sq / max(rowsum(sq), 1e-12). One block per batch, 256 threads.
// ---------------------------------------------------------------------------
template<int NN>
__global__ void adj_kernel(const float* __restrict__ QX, const float* __restrict__ KX,
                           float* __restrict__ ADJ, int d)
{
    constexpr int NP  = NN * NN;
    constexpr int PPT = (NP + 255) / 256;
    constexpr int DK  = 32;
    __shared__ float qs[NN][DK + 1];
    __shared__ float ks[NN][DK + 1];
    __shared__ float rowsum[NN];

    const int b = blockIdx.x, tid = threadIdx.x;
    const float* q = QX + (size_t)b * NN * d;
    const float* k = KX + (size_t)b * NN * d;

    float acc[PPT];
    #pragma unroll
    for (int p = 0; p < PPT; p++) acc[p] = 0.f;

    for (int k0 = 0; k0 < d; k0 += DK) {
        __syncthreads();
        for (int idx = tid; idx < NN * DK; idx += 256) {
            int n = idx / DK, kk = idx % DK;
            qs[n][kk] = q[(size_t)n * d + k0 + kk];
            ks[n][kk] = k[(size_t)n * d + k0 + kk];
        }
        __syncthreads();
        #pragma unroll
        for (int p = 0; p < PPT; p++) {
            int pair = tid + p * 256;
            if (pair < NP) {
                int n = pair / NN, m = pair % NN;
                float a = acc[p];
                #pragma unroll
                for (int kk = 0; kk < DK; kk++) a += qs[n][kk] * ks[m][kk];
                acc[p] = a;
            }
        }
    }

    if (tid < NN) rowsum[tid] = 0.f;
    __syncthreads();
    float sq[PPT];
    #pragma unroll
    for (int p = 0; p < PPT; p++) {
        int pair = tid + p * 256;
        if (pair < NP) {
            sq[p] = acc[p] * acc[p];
            atomicAdd(&rowsum[pair / NN], sq[p]);
        }
    }
    __syncthreads();
    #pragma unroll
    for (int p = 0; p < PPT; p++) {
        int pair = tid + p * 256;
        if (pair < NP)
            ADJ[(size_t)b * NP + pair] = sq[p] / fmaxf(rowsum[pair / NN], 1e-12f);
    }
}

// ---------------------------------------------------------------------------
// h[b,n,:] = sum_m adj[b,n,m] * xw[b,m,:]. One block per batch.
// ---------------------------------------------------------------------------
template<int NN>
__global__ void adjmm_kernel(const float* __restrict__ ADJ, const float* __restrict__ XW,
                             float* __restrict__ H, int d)
{
    constexpr int CJ  = 128;
    constexpr int RG  = 256 / CJ;
    constexpr int NPT = (NN + RG - 1) / RG;
    __shared__ float adjs[NN * NN];
    __shared__ float xws[NN][CJ];

    const int b = blockIdx.x, tid = threadIdx.x;
    const int j = tid & (CJ - 1);
    const int r = tid >> 7;

    for (int idx = tid; idx < NN * NN; idx += 256)
        adjs[idx] = ADJ[(size_t)b * NN * NN + idx];

    const float* xw = XW + (size_t)b * NN * d;
    float*       h  = H  + (size_t)b * NN * d;

    for (int jc = 0; jc < d; jc += CJ) {
        __syncthreads();
        for (int idx = tid; idx < NN * CJ; idx += 256) {
            int m = idx / CJ, jj = idx % CJ;
            xws[m][jj] = xw[(size_t)m * d + jc + jj];
        }
        __syncthreads();

        float acc[NPT];
        #pragma unroll
        for (int i = 0; i < NPT; i++) acc[i] = 0.f;
        #pragma unroll
        for (int m = 0; m < NN; m++) {
            float v = xws[m][j];
            #pragma unroll
            for (int i = 0; i < NPT; i++)
                acc[i] += adjs[(r + i * RG) * NN + m] * v;
        }
        #pragma unroll
        for (int i = 0; i < NPT; i++) {
            int n = r + i * RG;
            if (n < NN) h[(size_t)n * d + jc + j] = acc[i];
        }
    }
}

// ---------------------------------------------------------------------------
// x = relu(LayerNorm(h) * g + b), one block per row, 256 threads, d=768
// ---------------------------------------------------------------------------
__global__ void ln_relu_kernel(const float* __restrict__ H, const float* __restrict__ g,
                               const float* __restrict__ bb, float* __restrict__ O, int d)
{
    const int row = blockIdx.x;
    const float* h = H + (size_t)row * d;
    float s = 0.f, ss = 0.f;
    float vals[3];
    int cnt = 0;
    for (int jj = threadIdx.x; jj < d; jj += 256) {
        float v = h[jj];
        vals[cnt++] = v;
        s += v; ss += v * v;
    }
    #pragma unroll
    for (int o = 16; o; o >>= 1) {
        s  += __shfl_xor_sync(0xffffffffu, s, o);
        ss += __shfl_xor_sync(0xffffffffu, ss, o);
    }
    __shared__ float reds[8], redss[8], smu[1], srs[1];
    int w = threadIdx.x >> 5, l = threadIdx.x & 31;
    if (l == 0) { reds[w] = s; redss[w] = ss; }
    __syncthreads();
    if (threadIdx.x == 0) {
        float ts = 0.f, tss = 0.f;
        #pragma unroll
        for (int i = 0; i < 8; i++) { ts += reds[i]; tss += redss[i]; }
        float mu  = ts / d;
        float var = tss / d - mu * mu;
        smu[0] = mu;
        srs[0] = rsqrtf(var + 1e-5f);
    }
    __syncthreads();
    float mu = smu[0], rs = srs[0];
    cnt = 0;
    for (int jj = threadIdx.x; jj < d; jj += 256) {
        float v = (vals[cnt++] - mu) * rs * g[jj] + bb[jj];
        O[(size_t)row * d + jj] = fmaxf(v, 0.f);
    }
}

// ---------------------------------------------------------------------------
// Mean over nodes: out[b,j] = (1/NN) sum_n x[b,n,j]
// ---------------------------------------------------------------------------
template<int NN>
__global__ void mean_kernel(const float* __restrict__ X, float* __restrict__ O, int d)
{
    const int b = blockIdx.x;
    for (int jj = threadIdx.x; jj < d; jj += 256) {
        float s = 0.f;
        #pragma unroll 10
        for (int i = 0; i < NN; i++)
            s += X[((size_t)b * NN + i) * d + jj];
        O[(size_t)b * d + jj] = s * (1.f / NN);
    }
}

__global__ void concat_kernel(const float* __restrict__ a, const float* __restrict__ g2,
                              float* __restrict__ y, int d)
{
    const int i = blockIdx.x;
    for (int jj = threadIdx.x; jj < d; jj += 256) {
        y[(size_t)i * 2 * d + jj]     = a[(size_t)i * d + jj];
        y[(size_t)i * 2 * d + d + jj] = g2[(size_t)i * d + jj];
    }
}

// ---------------------------------------------------------------------------
// Host side
// ---------------------------------------------------------------------------
static inline dim3 gemm_grid(int M, int N) {
    return dim3((N + 127) / 128, (M + 127) / 128);
}

template<int NN>
static void run_graph(const float* x_in, int Bt,
                      const float* wqT, const float* wq_b,
                      const float* wkT, const float* wk_b,
                      const float* gcn_w, const float* ln_g, const float* ln_b,
                      float* p_qx, float* p_kx, float* p_xw, float* p_h,
                      float* p_x, float* p_adj, float* out_mean)
{
    const int M = Bt * NN;
    gemm_tf32<false><<<gemm_grid(M, NF), 256>>>(x_in, wqT, wq_b, p_qx, M, NF, NF);
    gemm_tf32<false><<<gemm_grid(M, NF), 256>>>(x_in, wkT, wk_b, p_kx, M, NF, NF);
    adj_kernel<NN><<<Bt, 256>>>(p_qx, p_kx, p_adj, NF);
    gemm_tf32<false><<<gemm_grid(M, NF), 256>>>(x_in, gcn_w, nullptr, p_xw, M, NF, NF);
    adjmm_kernel<NN><<<Bt, 256>>>(p_adj, p_xw, p_h, NF);
    ln_relu_kernel<<<M, 256>>>(p_h, ln_g, ln_b, p_x, NF);
    gemm_tf32<false><<<gemm_grid(M, NF), 256>>>(p_x, gcn_w + (size_t)NF * NF, nullptr, p_xw, M, NF, NF);
    adjmm_kernel<NN><<<Bt, 256>>>(p_adj, p_xw, p_h, NF);
    ln_relu_kernel<<<M, 256>>>(p_h, ln_g + NF, ln_b + NF, p_x, NF);
    mean_kernel<NN><<<Bt, 256>>>(p_x, out_mean, NF);
}

extern "C" void kernel_launch(void* const* d_in, const int* in_sizes, int n_in,
                              void* d_out, int out_size)
{
    const float* feats  = (const float*)d_in[0];   // [16,32,50,768]
    const float* fglob  = (const float*)d_in[1];   // [16,768]
    const float* wq_w   = (const float*)d_in[3];
    const float* wq_b   = (const float*)d_in[4];
    const float* wk_w   = (const float*)d_in[5];
    const float* wk_b   = (const float*)d_in[6];
    const float* gcn_w  = (const float*)d_in[7];   // [2,768,768]
    const float* ln_g   = (const float*)d_in[8];
    const float* ln_b   = (const float*)d_in[9];
    const float* fc1_w  = (const float*)d_in[10];  // [768,1536]
    const float* fc1_b  = (const float*)d_in[11];
    const float* fc2_w  = (const float*)d_in[12];  // [400,768]
    const float* fc2_b  = (const float*)d_in[13];
    float* out = (float*)d_out;                    // logits[16*400] then y[16*1536]

    float *p_qx, *p_kx, *p_xw, *p_h, *p_x, *p_adj, *p_mean, *p_mean2, *p_hc;
    float *p_wqT, *p_wkT, *p_fc1T, *p_fc2T;
    cudaGetSymbolAddress((void**)&p_qx,   g_qx);
    cudaGetSymbolAddress((void**)&p_kx,   g_kx);
    cudaGetSymbolAddress((void**)&p_xw,   g_xw);
    cudaGetSymbolAddress((void**)&p_h,    g_h);
    cudaGetSymbolAddress((void**)&p_x,    g_x);
    cudaGetSymbolAddress((void**)&p_adj,  g_adj);
    cudaGetSymbolAddress((void**)&p_mean, g_mean);
    cudaGetSymbolAddress((void**)&p_mean2,g_mean2);
    cudaGetSymbolAddress((void**)&p_hc,   g_hc);
    cudaGetSymbolAddress((void**)&p_wqT,  g_wqT);
    cudaGetSymbolAddress((void**)&p_wkT,  g_wkT);
    cudaGetSymbolAddress((void**)&p_fc1T, g_fc1T);
    cudaGetSymbolAddress((void**)&p_fc2T, g_fc2T);

    // ---- pre-transpose weights used as B^T into [K][N] form ----
    dim3 tb(32, 8);
    transpose_kernel<<<dim3(NF / 32, NF / 32), tb>>>(wq_w, p_wqT, NF, NF);
    transpose_kernel<<<dim3(NF / 32, NF / 32), tb>>>(wk_w, p_wkT, NF, NF);
    transpose_kernel<<<dim3(NF2 / 32, NF / 32), tb>>>(fc1_w, p_fc1T, NF, NF2);
    transpose_kernel<<<dim3(NF / 32, (NC + 31) / 32), tb>>>(fc2_w, p_fc2T, NC, NF);

    // ---- graph pass 1: [512, 50, 768] -> [512, 768] ----
    run_graph<NN1>(feats, NB1, p_wqT, wq_b, p_wkT, wk_b, gcn_w, ln_g, ln_b,
                   p_qx, p_kx, p_xw, p_h, p_x, p_adj, p_mean);

    // ---- graph pass 2: [16, 32, 768] -> [16, 768] ----
    run_graph<NN2>(p_mean, NB2, p_wqT, wq_b, p_wkT, wk_b, gcn_w, ln_g, ln_b,
                   p_qx, p_kx, p_xw, p_h, p_x, p_adj, p_mean2);

    // ---- classifier ----
    float* y_out = out + NB2 * NC;   // y region: [16, 1536]
    concat_kernel<<<NB2, 256>>>(p_mean2, fglob, y_out, NF);
    // h = relu(y @ fc1_w^T + fc1_b) : [16,1536] @ [1536,768]
    gemm_tf32<true ><<<gemm_grid(NB2, NF), 256>>>(y_out, p_fc1T, fc1_b, p_hc, NB2, NF, NF2);
    // logits = h @ fc2_w^T + fc2_b  : [16,768] @ [768,400]
    gemm_tf32<false><<<gemm_grid(NB2, NC), 256>>>(p_hc, p_fc2T, fc2_b, out, NB2, NC, NF);
}

// round 3
// speedup vs baseline: 3.3147x; 1.4549x over previous
#include <cuda_runtime.h>
#include <cstdint>

// ---------------------------------------------------------------------------
// Problem constants
// ---------------------------------------------------------------------------
#define NF   768
#define NB1  512          // batch for graph pass 1 (N*FR)
#define NN1  50           // nodes graph 1
#define NB2  16           // batch graph 2
#define NN2  32           // nodes graph 2
#define M1   (NB1*NN1)    // 25600 rows
#define NC   400
#define NF2  (2*NF)
#define NQKW 2304         // combined q|k|xw projection width

// ---------------------------------------------------------------------------
// Scratch (device globals; no runtime allocation allowed)
// ---------------------------------------------------------------------------
__device__ float g_qkxw[(size_t)M1 * NQKW];   // qx | kx | xw, ld=2304
__device__ float g_xw  [(size_t)M1 * NF];
__device__ float g_x   [(size_t)M1 * NF];
__device__ float g_adj [(size_t)NB1 * NN1 * NN1];
__device__ float g_mean[(size_t)NB1 * NF];
__device__ float g_mean2[(size_t)NB2 * NF];
__device__ float g_hc  [(size_t)NB2 * NF];
__device__ float g_wcomb[(size_t)NF * NQKW];  // [K=768][N=2304]: wqT|wkT|W0
__device__ float g_bcomb[NQKW];
__device__ float g_fc1T[(size_t)NF2 * NF];
__device__ float g_fc2T[(size_t)NF * NC];

// ---------------------------------------------------------------------------
// tf32 helpers
// ---------------------------------------------------------------------------
__device__ __forceinline__ uint32_t f2tf32(float f) {
    uint32_t r;
    asm("cvt.rna.tf32.f32 %0, %1;" : "=r"(r) : "f"(f));
    return r;
}

__device__ __forceinline__ void mma_tf32(float* d, const uint32_t* a, const uint32_t* b) {
    asm volatile(
        "mma.sync.aligned.m16n8k8.row.col.f32.tf32.tf32.f32 "
        "{%0,%1,%2,%3}, {%4,%5,%6,%7}, {%8,%9}, {%0,%1,%2,%3};"
        : "+f"(d[0]), "+f"(d[1]), "+f"(d[2]), "+f"(d[3])
        : "r"(a[0]), "r"(a[1]), "r"(a[2]), "r"(a[3]), "r"(b[0]), "r"(b[1]));
}

// ---------------------------------------------------------------------------
// TF32 GEMM: C[M,N] = A[M,K] @ B[K,N] + bias, optional ReLU. lda/ldb/ldc.
// 128x128x32 block tile, 256 threads (8 warps of 64x32), m16n8k8 tf32 mma.
// K must be a multiple of 32.
// ---------------------------------------------------------------------------
template<bool RELU>
__global__ __launch_bounds__(256, 2)
void gemm_tf32(const float* __restrict__ A, const float* __restrict__ B,
               const float* __restrict__ bias, float* __restrict__ C,
               int M, int N, int K, int lda, int ldb, int ldc)
{
    constexpr int BM = 128, BN = 128, BK = 32;
    constexpr int AKP = 40;
    constexpr int BNP = 132;

    __shared__ uint32_t As[BM * AKP];
    __shared__ uint32_t Bs[BK * BNP];

    const int tid  = threadIdx.x;
    const int wid  = tid >> 5;
    const int lane = tid & 31;
    const int gid  = lane >> 2;
    const int cq   = lane & 3;
    const int wm   = (wid >> 2) * 64;
    const int wn   = (wid & 3) * 32;

    const int row0 = blockIdx.y * BM;
    const int col0 = blockIdx.x * BN;

    float acc[4][4][4];
    #pragma unroll
    for (int i = 0; i < 4; i++)
        #pragma unroll
        for (int j = 0; j < 4; j++)
            #pragma unroll
            for (int q = 0; q < 4; q++) acc[i][j][q] = 0.f;

    for (int k0 = 0; k0 < K; k0 += BK) {
        #pragma unroll
        for (int i = 0; i < 4; i++) {
            int u  = tid + i * 256;
            int m  = u >> 3;
            int kq = u & 7;
            int gm = row0 + m;
            float4 v = make_float4(0.f, 0.f, 0.f, 0.f);
            if (gm < M) v = *reinterpret_cast<const float4*>(A + (size_t)gm * lda + k0 + 4 * kq);
            int base = m * AKP + 8 * (kq >> 1) + (kq & 1);
            As[base + 0] = f2tf32(v.x);
            As[base + 2] = f2tf32(v.y);
            As[base + 4] = f2tf32(v.z);
            As[base + 6] = f2tf32(v.w);
        }
        #pragma unroll
        for (int i = 0; i < 4; i++) {
            int u  = tid + i * 256;
            int k  = u >> 5;
            int nq = u & 31;
            int gn = col0 + 4 * nq;
            const float* bp = B + (size_t)(k0 + k) * ldb + gn;
            float x0 = (gn + 0 < N) ? bp[0] : 0.f;
            float x1 = (gn + 1 < N) ? bp[1] : 0.f;
            float x2 = (gn + 2 < N) ? bp[2] : 0.f;
            float x3 = (gn + 3 < N) ? bp[3] : 0.f;
            int base = k * BNP + 4 * nq;
            Bs[base + 0] = f2tf32(x0);
            Bs[base + 1] = f2tf32(x1);
            Bs[base + 2] = f2tf32(x2);
            Bs[base + 3] = f2tf32(x3);
        }
        __syncthreads();

        #pragma unroll
        for (int s = 0; s < 4; s++) {
            uint32_t af[4][4];
            #pragma unroll
            for (int mt = 0; mt < 4; mt++) {
                int r0 = wm + mt * 16 + gid;
                uint2 t0 = *reinterpret_cast<const uint2*>(&As[(r0    ) * AKP + 8 * s + 2 * cq]);
                uint2 t1 = *reinterpret_cast<const uint2*>(&As[(r0 + 8) * AKP + 8 * s + 2 * cq]);
                af[mt][0] = t0.x; af[mt][1] = t1.x; af[mt][2] = t0.y; af[mt][3] = t1.y;
            }
            uint32_t bf[4][2];
            #pragma unroll
            for (int nt = 0; nt < 4; nt++) {
                int cn = wn + nt * 8 + gid;
                bf[nt][0] = Bs[(8 * s + cq    ) * BNP + cn];
                bf[nt][1] = Bs[(8 * s + cq + 4) * BNP + cn];
            }
            #pragma unroll
            for (int mt = 0; mt < 4; mt++)
                #pragma unroll
                for (int nt = 0; nt < 4; nt++)
                    mma_tf32(acc[mt][nt], af[mt], bf[nt]);
        }
        __syncthreads();
    }

    #pragma unroll
    for (int mt = 0; mt < 4; mt++) {
        int rlo = row0 + wm + mt * 16 + gid;
        int rhi = rlo + 8;
        #pragma unroll
        for (int nt = 0; nt < 4; nt++) {
            int cc = col0 + wn + nt * 8 + 2 * cq;
            float b0 = 0.f, b1 = 0.f;
            if (bias) {
                if (cc     < N) b0 = bias[cc];
                if (cc + 1 < N) b1 = bias[cc + 1];
            }
            float v;
            if (rlo < M) {
                if (cc < N) {
                    v = acc[mt][nt][0] + b0; if (RELU) v = fmaxf(v, 0.f);
                    C[(size_t)rlo * ldc + cc] = v;
                }
                if (cc + 1 < N) {
                    v = acc[mt][nt][1] + b1; if (RELU) v = fmaxf(v, 0.f);
                    C[(size_t)rlo * ldc + cc + 1] = v;
                }
            }
            if (rhi < M) {
                if (cc < N) {
                    v = acc[mt][nt][2] + b0; if (RELU) v = fmaxf(v, 0.f);
                    C[(size_t)rhi * ldc + cc] = v;
                }
                if (cc + 1 < N) {
                    v = acc[mt][nt][3] + b1; if (RELU) v = fmaxf(v, 0.f);
                    C[(size_t)rhi * ldc + cc + 1] = v;
                }
            }
        }
    }
}

// ---------------------------------------------------------------------------
// adj_mma: per batch b (one CTA), split-tf32 (fp32-accurate) 64x64 dot tile:
// dot[n,m] = <qx[b,n,:], kx[b,m,:]>, adj = dot^2 / max(rowsum(dot^2), 1e-12)
// ---------------------------------------------------------------------------
template<int NN>
__global__ __launch_bounds__(256, 2)
void adj_mma(const float* __restrict__ QX, const float* __restrict__ KX, int ld,
             float* __restrict__ ADJ)
{
    __shared__ __align__(16) uint32_t sbuf[9728];
    uint32_t* qh = sbuf;           // [64*40] permuted A layout
    uint32_t* ql = sbuf + 2560;
    uint32_t* kh = sbuf + 5120;    // [64*36] natural [n][k]
    uint32_t* kl = sbuf + 7424;

    const int b = blockIdx.x, tid = threadIdx.x;
    const int wid = tid >> 5, lane = tid & 31;
    const int gid = lane >> 2, cq = lane & 3;
    const int wm = (wid >> 2) * 32, wn = (wid & 3) * 16;

    const float* q = QX + (size_t)b * NN * ld;
    const float* k = KX + (size_t)b * NN * ld;

    float acc[2][2][4];
    #pragma unroll
    for (int a = 0; a < 2; a++)
        #pragma unroll
        for (int c = 0; c < 2; c++)
            #pragma unroll
            for (int e = 0; e < 4; e++) acc[a][c][e] = 0.f;

    for (int k0 = 0; k0 < NF; k0 += 32) {
        __syncthreads();
        // stage q (hi/lo, k-permuted within 8)
        #pragma unroll
        for (int i = 0; i < 2; i++) {
            int u = tid + i * 256;        // 512 float4 slots
            int m = u >> 3, kq = u & 7;
            float4 v = make_float4(0.f, 0.f, 0.f, 0.f);
            if (m < NN) v = *reinterpret_cast<const float4*>(q + (size_t)m * ld + k0 + 4 * kq);
            int base = m * 40 + 8 * (kq >> 1) + (kq & 1);
            float xs[4] = {v.x, v.y, v.z, v.w};
            #pragma unroll
            for (int j = 0; j < 4; j++) {
                uint32_t hi = f2tf32(xs[j]);
                qh[base + 2 * j] = hi;
                ql[base + 2 * j] = f2tf32(xs[j] - __uint_as_float(hi));
            }
        }
        // stage k (hi/lo, natural [n][k] with pad 36)
        #pragma unroll
        for (int i = 0; i < 2; i++) {
            int u = tid + i * 256;
            int n = u >> 3, kq = u & 7;
            float4 v = make_float4(0.f, 0.f, 0.f, 0.f);
            if (n < NN) v = *reinterpret_cast<const float4*>(k + (size_t)n * ld + k0 + 4 * kq);
            int base = n * 36 + 4 * kq;
            float xs[4] = {v.x, v.y, v.z, v.w};
            #pragma unroll
            for (int j = 0; j < 4; j++) {
                uint32_t hi = f2tf32(xs[j]);
                kh[base + j] = hi;
                kl[base + j] = f2tf32(xs[j] - __uint_as_float(hi));
            }
        }
        __syncthreads();

        #pragma unroll
        for (int s = 0; s < 4; s++) {
            uint32_t ah[2][4], al[2][4], bh[2][2], bl[2][2];
            #pragma unroll
            for (int mt = 0; mt < 2; mt++) {
                int r0 = wm + mt * 16 + gid;
                uint2 t0 = *reinterpret_cast<const uint2*>(&qh[(r0    ) * 40 + 8 * s + 2 * cq]);
                uint2 t1 = *reinterpret_cast<const uint2*>(&qh[(r0 + 8) * 40 + 8 * s + 2 * cq]);
                ah[mt][0] = t0.x; ah[mt][1] = t1.x; ah[mt][2] = t0.y; ah[mt][3] = t1.y;
                uint2 u0 = *reinterpret_cast<const uint2*>(&ql[(r0    ) * 40 + 8 * s + 2 * cq]);
                uint2 u1 = *reinterpret_cast<const uint2*>(&ql[(r0 + 8) * 40 + 8 * s + 2 * cq]);
                al[mt][0] = u0.x; al[mt][1] = u1.x; al[mt][2] = u0.y; al[mt][3] = u1.y;
            }
            #pragma unroll
            for (int nt = 0; nt < 2; nt++) {
                int n = wn + 8 * nt + gid;
                bh[nt][0] = kh[n * 36 + 8 * s + cq];
                bh[nt][1] = kh[n * 36 + 8 * s + cq + 4];
                bl[nt][0] = kl[n * 36 + 8 * s + cq];
                bl[nt][1] = kl[n * 36 + 8 * s + cq + 4];
            }
            #pragma unroll
            for (int mt = 0; mt < 2; mt++)
                #pragma unroll
                for (int nt = 0; nt < 2; nt++) {
                    mma_tf32(acc[mt][nt], ah[mt], bh[nt]);
                    mma_tf32(acc[mt][nt], ah[mt], bl[nt]);
                    mma_tf32(acc[mt][nt], al[mt], bh[nt]);
                }
        }
    }
    __syncthreads();

    // overlay: sq [64*68], rinv [64]
    float* sq   = reinterpret_cast<float*>(sbuf);
    float* rinv = reinterpret_cast<float*>(sbuf) + 4400;

    #pragma unroll
    for (int mt = 0; mt < 2; mt++)
        #pragma unroll
        for (int nt = 0; nt < 2; nt++) {
            int r = wm + 16 * mt + gid;
            int c = wn + 8 * nt + 2 * cq;
            sq[(r    ) * 68 + c    ] = acc[mt][nt][0] * acc[mt][nt][0];
            sq[(r    ) * 68 + c + 1] = acc[mt][nt][1] * acc[mt][nt][1];
            sq[(r + 8) * 68 + c    ] = acc[mt][nt][2] * acc[mt][nt][2];
            sq[(r + 8) * 68 + c + 1] = acc[mt][nt][3] * acc[mt][nt][3];
        }
    __syncthreads();

    for (int r = wid; r < NN; r += 8) {
        float s = sq[r * 68 + lane] + sq[r * 68 + 32 + lane];
        #pragma unroll
        for (int o = 16; o; o >>= 1) s += __shfl_xor_sync(0xffffffffu, s, o);
        if (lane == 0) rinv[r] = 1.f / fmaxf(s, 1e-12f);
    }
    __syncthreads();

    for (int idx = tid; idx < NN * NN; idx += 256) {
        int n = idx / NN, m = idx - n * NN;
        ADJ[(size_t)b * NN * NN + idx] = sq[n * 68 + m] * rinv[n];
    }
}

// ---------------------------------------------------------------------------
// Fused GCN layer: per-batch CTA of 768 threads (thread = one feature column).
//   h = adj @ xw   (exact fp32, xw column in registers)
//   x = relu(LayerNorm(h) * g + b)
//   MEAN: write column mean over nodes instead of x.
// Dynamic smem: adjs[NN*NN] | mu[NN] | rs[NN] | h[NN*768]
// ---------------------------------------------------------------------------
template<int NN, bool MEAN>
__global__ __launch_bounds__(768, 1)
void gcn_fused(const float* __restrict__ ADJ, const float* __restrict__ XW, int ldxw,
               const float* __restrict__ g, const float* __restrict__ bb,
               float* __restrict__ OUT)
{
    extern __shared__ float sm[];
    float* adjs = sm;
    float* mu   = sm + NN * NN;
    float* rs   = mu + NN;
    float* h    = rs + NN;

    const int b = blockIdx.x;
    const int j = threadIdx.x;
    const int w = j >> 5, lane = j & 31;

    float xcol[NN];
    #pragma unroll
    for (int m = 0; m < NN; m++)
        xcol[m] = XW[((size_t)b * NN + m) * ldxw + j];

    for (int idx = j; idx < NN * NN; idx += 768)
        adjs[idx] = ADJ[(size_t)b * NN * NN + idx];
    __syncthreads();

    for (int n = 0; n < NN; n++) {
        float s = 0.f;
        #pragma unroll
        for (int m = 0; m < NN; m++)
            s += adjs[n * NN + m] * xcol[m];
        h[n * NF + j] = s;
    }
    __syncthreads();

    for (int r = w; r < NN; r += 24) {
        float s = 0.f, ss = 0.f;
        #pragma unroll
        for (int c = lane; c < NF; c += 32) {
            float v = h[r * NF + c];
            s += v; ss += v * v;
        }
        #pragma unroll
        for (int o = 16; o; o >>= 1) {
            s  += __shfl_xor_sync(0xffffffffu, s, o);
            ss += __shfl_xor_sync(0xffffffffu, ss, o);
        }
        if (lane == 0) {
            float m_ = s * (1.f / NF);
            mu[r] = m_;
            rs[r] = rsqrtf(ss * (1.f / NF) - m_ * m_ + 1e-5f);
        }
    }
    __syncthreads();

    const float gg = g[j], bv = bb[j];
    if (MEAN) {
        float macc = 0.f;
        for (int n = 0; n < NN; n++) {
            float v = (h[n * NF + j] - mu[n]) * rs[n] * gg + bv;
            macc += fmaxf(v, 0.f);
        }
        OUT[(size_t)b * NF + j] = macc * (1.f / NN);
    } else {
        for (int n = 0; n < NN; n++) {
            float v = (h[n * NF + j] - mu[n]) * rs[n] * gg + bv;
            OUT[((size_t)b * NN + n) * NF + j] = fmaxf(v, 0.f);
        }
    }
}

// ---------------------------------------------------------------------------
// Transpose: out[c][r] (with ld + col offset) = in[r][c]
// ---------------------------------------------------------------------------
__global__ void transpose_kernel(const float* __restrict__ in, float* __restrict__ out,
                                 int R, int C, int ldo, int col_off)
{
    __shared__ float t[32][33];
    int bx = blockIdx.x * 32, by = blockIdx.y * 32;
    int x = bx + threadIdx.x;
    for (int i = threadIdx.y; i < 32; i += 8) {
        int y = by + i;
        t[i][threadIdx.x] = (y < R && x < C) ? in[(size_t)y * C + x] : 0.f;
    }
    __syncthreads();
    int ox = by + threadIdx.x;
    for (int i = threadIdx.y; i < 32; i += 8) {
        int oy = bx + i;
        if (oy < C && ox < R) out[(size_t)oy * ldo + col_off + ox] = t[threadIdx.x][i];
    }
}

// copy W0 [768][768] into wcomb cols [1536..2304)
__global__ void copy_w0_kernel(const float* __restrict__ w0, float* __restrict__ wcomb)
{
    int k = blockIdx.x;
    for (int n = threadIdx.x; n < NF; n += 256)
        wcomb[(size_t)k * NQKW + 1536 + n] = w0[(size_t)k * NF + n];
}

// combined bias: [wq_b | wk_b | 0]
__global__ void bias_comb_kernel(const float* __restrict__ qb, const float* __restrict__ kb,
                                 float* __restrict__ bc)
{
    int j = blockIdx.x * 256 + threadIdx.x;
    if (j < NQKW)
        bc[j] = (j < NF) ? qb[j] : (j < 2 * NF ? kb[j - NF] : 0.f);
}

__global__ void concat_kernel(const float* __restrict__ a, const float* __restrict__ g2,
                              float* __restrict__ y, int d)
{
    const int i = blockIdx.x;
    for (int jj = threadIdx.x; jj < d; jj += 256) {
        y[(size_t)i * 2 * d + jj]     = a[(size_t)i * d + jj];
        y[(size_t)i * 2 * d + d + jj] = g2[(size_t)i * d + jj];
    }
}

// ---------------------------------------------------------------------------
// Host side
// ---------------------------------------------------------------------------
static inline dim3 gemm_grid(int M, int N) {
    return dim3((N + 127) / 128, (M + 127) / 128);
}

template<int NN>
static void run_graph(const float* x_in, int Bt,
                      const float* wcomb, const float* bcomb,
                      const float* gcn_w, const float* ln_g, const float* ln_b,
                      float* p_qkxw, float* p_xw, float* p_x, float* p_adj,
                      float* out_mean, size_t sm_fused)
{
    const int M = Bt * NN;
    // fused q|k|xw projection: [M,768] @ [768,2304]
    gemm_tf32<false><<<gemm_grid(M, NQKW), 256>>>(x_in, wcomb, bcomb, p_qkxw,
                                                  M, NQKW, NF, NF, NQKW, NQKW);
    adj_mma<NN><<<Bt, 256>>>(p_qkxw, p_qkxw + NF, NQKW, p_adj);
    // layer 0: fused adj@xw + LN + ReLU
    gcn_fused<NN, false><<<Bt, 768, sm_fused>>>(p_adj, p_qkxw + 2 * NF, NQKW,
                                                ln_g, ln_b, p_x);
    // layer 1 GEMM
    gemm_tf32<false><<<gemm_grid(M, NF), 256>>>(p_x, gcn_w + (size_t)NF * NF, nullptr, p_xw,
                                                M, NF, NF, NF, NF, NF);
    // layer 1 fused + node-mean
    gcn_fused<NN, true><<<Bt, 768, sm_fused>>>(p_adj, p_xw, NF,
                                               ln_g + NF, ln_b + NF, out_mean);
}

extern "C" void kernel_launch(void* const* d_in, const int* in_sizes, int n_in,
                              void* d_out, int out_size)
{
    const float* feats  = (const float*)d_in[0];   // [16,32,50,768]
    const float* fglob  = (const float*)d_in[1];   // [16,768]
    const float* wq_w   = (const float*)d_in[3];
    const float* wq_b   = (const float*)d_in[4];
    const float* wk_w   = (const float*)d_in[5];
    const float* wk_b   = (const float*)d_in[6];
    const float* gcn_w  = (const float*)d_in[7];   // [2,768,768]
    const float* ln_g   = (const float*)d_in[8];
    const float* ln_b   = (const float*)d_in[9];
    const float* fc1_w  = (const float*)d_in[10];  // [768,1536]
    const float* fc1_b  = (const float*)d_in[11];
    const float* fc2_w  = (const float*)d_in[12];  // [400,768]
    const float* fc2_b  = (const float*)d_in[13];
    float* out = (float*)d_out;                    // logits[16*400] then y[16*1536]

    float *p_qkxw, *p_xw, *p_x, *p_adj, *p_mean, *p_mean2, *p_hc;
    float *p_wcomb, *p_bcomb, *p_fc1T, *p_fc2T;
    cudaGetSymbolAddress((void**)&p_qkxw, g_qkxw);
    cudaGetSymbolAddress((void**)&p_xw,   g_xw);
    cudaGetSymbolAddress((void**)&p_x,    g_x);
    cudaGetSymbolAddress((void**)&p_adj,  g_adj);
    cudaGetSymbolAddress((void**)&p_mean, g_mean);
    cudaGetSymbolAddress((void**)&p_mean2,g_mean2);
    cudaGetSymbolAddress((void**)&p_hc,   g_hc);
    cudaGetSymbolAddress((void**)&p_wcomb,g_wcomb);
    cudaGetSymbolAddress((void**)&p_bcomb,g_bcomb);
    cudaGetSymbolAddress((void**)&p_fc1T, g_fc1T);
    cudaGetSymbolAddress((void**)&p_fc2T, g_fc2T);

    const size_t sm50 = (size_t)(NN1 * NN1 + 2 * NN1 + NN1 * NF) * 4;   // 164,000 B
    const size_t sm32 = (size_t)(NN2 * NN2 + 2 * NN2 + NN2 * NF) * 4;   // 102,656 B
    cudaFuncSetAttribute(gcn_fused<NN1, false>, cudaFuncAttributeMaxDynamicSharedMemorySize, (int)sm50);
    cudaFuncSetAttribute(gcn_fused<NN1, true >, cudaFuncAttributeMaxDynamicSharedMemorySize, (int)sm50);
    cudaFuncSetAttribute(gcn_fused<NN2, false>, cudaFuncAttributeMaxDynamicSharedMemorySize, (int)sm32);
    cudaFuncSetAttribute(gcn_fused<NN2, true >, cudaFuncAttributeMaxDynamicSharedMemorySize, (int)sm32);

    // ---- build combined weights/bias ----
    dim3 tb(32, 8);
    transpose_kernel<<<dim3(NF / 32, NF / 32), tb>>>(wq_w, p_wcomb, NF, NF, NQKW, 0);
    transpose_kernel<<<dim3(NF / 32, NF / 32), tb>>>(wk_w, p_wcomb, NF, NF, NQKW, NF);
    copy_w0_kernel<<<NF, 256>>>(gcn_w, p_wcomb);
    bias_comb_kernel<<<(NQKW + 255) / 256, 256>>>(wq_b, wk_b, p_bcomb);
    transpose_kernel<<<dim3(NF2 / 32, NF / 32), tb>>>(fc1_w, p_fc1T, NF, NF2, NF, 0);
    transpose_kernel<<<dim3(NF / 32, (NC + 31) / 32), tb>>>(fc2_w, p_fc2T, NC, NF, NC, 0);

    // ---- graph pass 1: [512, 50, 768] -> [512, 768] ----
    run_graph<NN1>(feats, NB1, p_wcomb, p_bcomb, gcn_w, ln_g, ln_b,
                   p_qkxw, p_xw, p_x, p_adj, p_mean, sm50);

    // ---- graph pass 2: [16, 32, 768] -> [16, 768] ----
    run_graph<NN2>(p_mean, NB2, p_wcomb, p_bcomb, gcn_w, ln_g, ln_b,
                   p_qkxw, p_xw, p_x, p_adj, p_mean2, sm32);

    // ---- classifier ----
    float* y_out = out + NB2 * NC;   // y region: [16, 1536]
    concat_kernel<<<NB2, 256>>>(p_mean2, fglob, y_out, NF);
    gemm_tf32<true ><<<gemm_grid(NB2, NF), 256>>>(y_out, p_fc1T, fc1_b, p_hc,
                                                  NB2, NF, NF2, NF2, NF, NF);
    gemm_tf32<false><<<gemm_grid(NB2, NC), 256>>>(p_hc, p_fc2T, fc2_b, out,
                                                  NB2, NC, NF, NF, NC, NC);
}

// round 4
// speedup vs baseline: 3.7356x; 1.1270x over previous
#include <cuda_runtime.h>
#include <cstdint>

// ---------------------------------------------------------------------------
// Problem constants
// ---------------------------------------------------------------------------
#define NF   768
#define NB1  512
#define NN1  50
#define NB2  16
#define NN2  32
#define M1   (NB1*NN1)    // 25600
#define NC   400
#define NF2  (2*NF)
#define NZW  1536         // combined z|xw width

// ---------------------------------------------------------------------------
// Scratch (device globals)
// ---------------------------------------------------------------------------
__device__ float g_zxw [(size_t)M1 * NZW];    // z | xw, ld=1536
__device__ float g_xw  [(size_t)M1 * NF];
__device__ float g_x   [(size_t)M1 * NF];
__device__ float g_adj [(size_t)NB1 * NN1 * NN1];
__device__ float g_mean[(size_t)NB1 * NF];
__device__ float g_mean2[(size_t)NB2 * NF];
__device__ float g_hc  [(size_t)NB2 * NF];
__device__ float g_wcomb[(size_t)NF * NZW];   // [K=768][N=1536]: A | W0
__device__ float g_wqT [(size_t)NF * NF];
__device__ float g_fc1T[(size_t)NF2 * NF];
__device__ float g_fc2T[(size_t)NF * NC];
__device__ float g_cvec[2 * NF + 1];          // c1 | c2 | c3
__device__ float g_r1  [M1];
__device__ float g_r2  [M1];

// ---------------------------------------------------------------------------
// tf32 helpers
// ---------------------------------------------------------------------------
__device__ __forceinline__ uint32_t f2tf32(float f) {
    uint32_t r;
    asm("cvt.rna.tf32.f32 %0, %1;" : "=r"(r) : "f"(f));
    return r;
}

__device__ __forceinline__ void mma_tf32(float* d, const uint32_t* a, const uint32_t* b) {
    asm volatile(
        "mma.sync.aligned.m16n8k8.row.col.f32.tf32.tf32.f32 "
        "{%0,%1,%2,%3}, {%4,%5,%6,%7}, {%8,%9}, {%0,%1,%2,%3};"
        : "+f"(d[0]), "+f"(d[1]), "+f"(d[2]), "+f"(d[3])
        : "r"(a[0]), "r"(a[1]), "r"(a[2]), "r"(a[3]), "r"(b[0]), "r"(b[1]));
}

// ---------------------------------------------------------------------------
// Pipelined TF32 GEMM: C = A[M,K] @ B[K,N] + bias, optional ReLU.
// 128x128x32, 256 threads, double-buffered dynamic smem, A-tile reg prefetch,
// one __syncthreads per k-iter. K % 32 == 0.
// dynamic smem = 2*(128*40 + 32*132)*4 = 74752 B
// ---------------------------------------------------------------------------
#define GEMM_SMEM 74752

template<bool RELU>
__global__ __launch_bounds__(256, 2)
void gemm_tf32(const float* __restrict__ A, const float* __restrict__ B,
               const float* __restrict__ bias, float* __restrict__ C,
               int M, int N, int K, int lda, int ldb, int ldc)
{
    constexpr int BK = 32, AKP = 40, BNP = 132;
    constexpr int ASZ = 128 * AKP, BSZ = BK * BNP;
    extern __shared__ uint32_t smg[];

    const int tid  = threadIdx.x;
    const int wid  = tid >> 5, lane = tid & 31;
    const int gid  = lane >> 2, cq = lane & 3;
    const int wm   = (wid >> 2) * 64, wn = (wid & 3) * 32;
    const int row0 = blockIdx.y * 128, col0 = blockIdx.x * 128;
    const int NK   = K / BK;

    float acc[4][4][4];
    #pragma unroll
    for (int i = 0; i < 4; i++)
        #pragma unroll
        for (int j = 0; j < 4; j++)
            #pragma unroll
            for (int q = 0; q < 4; q++) acc[i][j][q] = 0.f;

    float4 rA[4];

    // prologue A load (k-block 0)
    #pragma unroll
    for (int i = 0; i < 4; i++) {
        int u = tid + i * 256, m = u >> 3, kq = u & 7;
        int gm = row0 + m;
        rA[i] = (gm < M) ? *reinterpret_cast<const float4*>(A + (size_t)gm * lda + 4 * kq)
                         : make_float4(0.f, 0.f, 0.f, 0.f);
    }

    for (int it = 0; it < NK; it++) {
        const int p = it & 1;
        uint32_t* Ap = smg + p * ASZ;
        uint32_t* Bp = smg + 2 * ASZ + p * BSZ;

        // store prefetched A tile (cvt to tf32, k-permuted)
        #pragma unroll
        for (int i = 0; i < 4; i++) {
            int u = tid + i * 256, m = u >> 3, kq = u & 7;
            int base = m * AKP + 8 * (kq >> 1) + (kq & 1);
            Ap[base + 0] = f2tf32(rA[i].x);
            Ap[base + 2] = f2tf32(rA[i].y);
            Ap[base + 4] = f2tf32(rA[i].z);
            Ap[base + 6] = f2tf32(rA[i].w);
        }
        // load + store B tile (L2-hot weights)
        #pragma unroll
        for (int i = 0; i < 4; i++) {
            int u = tid + i * 256, k = u >> 5, nq = u & 31;
            int gn = col0 + 4 * nq;
            const float* bp = B + (size_t)(it * BK + k) * ldb + gn;
            float x0 = (gn + 0 < N) ? bp[0] : 0.f;
            float x1 = (gn + 1 < N) ? bp[1] : 0.f;
            float x2 = (gn + 2 < N) ? bp[2] : 0.f;
            float x3 = (gn + 3 < N) ? bp[3] : 0.f;
            int base = k * BNP + 4 * nq;
            Bp[base + 0] = f2tf32(x0);
            Bp[base + 1] = f2tf32(x1);
            Bp[base + 2] = f2tf32(x2);
            Bp[base + 3] = f2tf32(x3);
        }
        // prefetch next A tile (latency hidden by mma below)
        if (it + 1 < NK) {
            #pragma unroll
            for (int i = 0; i < 4; i++) {
                int u = tid + i * 256, m = u >> 3, kq = u & 7;
                int gm = row0 + m;
                rA[i] = (gm < M)
                    ? *reinterpret_cast<const float4*>(A + (size_t)gm * lda + (it + 1) * BK + 4 * kq)
                    : make_float4(0.f, 0.f, 0.f, 0.f);
            }
        }
        __syncthreads();

        #pragma unroll
        for (int s = 0; s < 4; s++) {
            uint32_t af[4][4];
            #pragma unroll
            for (int mt = 0; mt < 4; mt++) {
                int r0 = wm + mt * 16 + gid;
                uint2 t0 = *reinterpret_cast<const uint2*>(&Ap[(r0    ) * AKP + 8 * s + 2 * cq]);
                uint2 t1 = *reinterpret_cast<const uint2*>(&Ap[(r0 + 8) * AKP + 8 * s + 2 * cq]);
                af[mt][0] = t0.x; af[mt][1] = t1.x; af[mt][2] = t0.y; af[mt][3] = t1.y;
            }
            uint32_t bf[4][2];
            #pragma unroll
            for (int nt = 0; nt < 4; nt++) {
                int cn = wn + nt * 8 + gid;
                bf[nt][0] = Bp[(8 * s + cq    ) * BNP + cn];
                bf[nt][1] = Bp[(8 * s + cq + 4) * BNP + cn];
            }
            #pragma unroll
            for (int mt = 0; mt < 4; mt++)
                #pragma unroll
                for (int nt = 0; nt < 4; nt++)
                    mma_tf32(acc[mt][nt], af[mt], bf[nt]);
        }
        // no trailing sync: next iter writes the other buffer; the single
        // barrier above orders sts(i+1) after mma(i-1) completion globally.
    }

    #pragma unroll
    for (int mt = 0; mt < 4; mt++) {
        int rlo = row0 + wm + mt * 16 + gid;
        int rhi = rlo + 8;
        #pragma unroll
        for (int nt = 0; nt < 4; nt++) {
            int cc = col0 + wn + nt * 8 + 2 * cq;
            float b0 = 0.f, b1 = 0.f;
            if (bias) {
                if (cc     < N) b0 = bias[cc];
                if (cc + 1 < N) b1 = bias[cc + 1];
            }
            float v;
            if (rlo < M) {
                if (cc < N) {
                    v = acc[mt][nt][0] + b0; if (RELU) v = fmaxf(v, 0.f);
                    C[(size_t)rlo * ldc + cc] = v;
                }
                if (cc + 1 < N) {
                    v = acc[mt][nt][1] + b1; if (RELU) v = fmaxf(v, 0.f);
                    C[(size_t)rlo * ldc + cc + 1] = v;
                }
            }
            if (rhi < M) {
                if (cc < N) {
                    v = acc[mt][nt][2] + b0; if (RELU) v = fmaxf(v, 0.f);
                    C[(size_t)rhi * ldc + cc] = v;
                }
                if (cc + 1 < N) {
                    v = acc[mt][nt][3] + b1; if (RELU) v = fmaxf(v, 0.f);
                    C[(size_t)rhi * ldc + cc + 1] = v;
                }
            }
        }
    }
}

// ---------------------------------------------------------------------------
// Split-tf32 GEMM (fp32-accurate), single-buffer. Used once for A = wqT @ wk.
// dynamic smem = GEMM_SMEM (same 74752: Ah|Al|Bh|Bl)
// ---------------------------------------------------------------------------
__global__ __launch_bounds__(256, 1)
void gemm_split(const float* __restrict__ A, const float* __restrict__ B,
                float* __restrict__ C, int M, int N, int K,
                int lda, int ldb, int ldc)
{
    constexpr int BK = 32, AKP = 40, BNP = 132;
    constexpr int ASZ = 128 * AKP, BSZ = BK * BNP;
    extern __shared__ uint32_t smg[];
    uint32_t* Ah = smg;
    uint32_t* Al = smg + ASZ;
    uint32_t* Bh = smg + 2 * ASZ;
    uint32_t* Bl = smg + 2 * ASZ + BSZ;

    const int tid  = threadIdx.x;
    const int wid  = tid >> 5, lane = tid & 31;
    const int gid  = lane >> 2, cq = lane & 3;
    const int wm   = (wid >> 2) * 64, wn = (wid & 3) * 32;
    const int row0 = blockIdx.y * 128, col0 = blockIdx.x * 128;

    float acc[4][4][4];
    #pragma unroll
    for (int i = 0; i < 4; i++)
        #pragma unroll
        for (int j = 0; j < 4; j++)
            #pragma unroll
            for (int q = 0; q < 4; q++) acc[i][j][q] = 0.f;

    for (int k0 = 0; k0 < K; k0 += BK) {
        __syncthreads();
        #pragma unroll
        for (int i = 0; i < 4; i++) {
            int u = tid + i * 256, m = u >> 3, kq = u & 7;
            int gm = row0 + m;
            float4 v = (gm < M) ? *reinterpret_cast<const float4*>(A + (size_t)gm * lda + k0 + 4 * kq)
                                : make_float4(0.f, 0.f, 0.f, 0.f);
            int base = m * AKP + 8 * (kq >> 1) + (kq & 1);
            float xs[4] = {v.x, v.y, v.z, v.w};
            #pragma unroll
            for (int j = 0; j < 4; j++) {
                uint32_t hi = f2tf32(xs[j]);
                Ah[base + 2 * j] = hi;
                Al[base + 2 * j] = f2tf32(xs[j] - __uint_as_float(hi));
            }
        }
        #pragma unroll
        for (int i = 0; i < 4; i++) {
            int u = tid + i * 256, k = u >> 5, nq = u & 31;
            int gn = col0 + 4 * nq;
            const float* bp = B + (size_t)(k0 + k) * ldb + gn;
            int base = k * BNP + 4 * nq;
            #pragma unroll
            for (int j = 0; j < 4; j++) {
                float x = (gn + j < N) ? bp[j] : 0.f;
                uint32_t hi = f2tf32(x);
                Bh[base + j] = hi;
                Bl[base + j] = f2tf32(x - __uint_as_float(hi));
            }
        }
        __syncthreads();

        #pragma unroll
        for (int s = 0; s < 4; s++) {
            uint32_t ah[4][4], al[4][4];
            #pragma unroll
            for (int mt = 0; mt < 4; mt++) {
                int r0 = wm + mt * 16 + gid;
                uint2 t0 = *reinterpret_cast<const uint2*>(&Ah[(r0    ) * AKP + 8 * s + 2 * cq]);
                uint2 t1 = *reinterpret_cast<const uint2*>(&Ah[(r0 + 8) * AKP + 8 * s + 2 * cq]);
                ah[mt][0] = t0.x; ah[mt][1] = t1.x; ah[mt][2] = t0.y; ah[mt][3] = t1.y;
                uint2 u0 = *reinterpret_cast<const uint2*>(&Al[(r0    ) * AKP + 8 * s + 2 * cq]);
                uint2 u1 = *reinterpret_cast<const uint2*>(&Al[(r0 + 8) * AKP + 8 * s + 2 * cq]);
                al[mt][0] = u0.x; al[mt][1] = u1.x; al[mt][2] = u0.y; al[mt][3] = u1.y;
            }
            uint32_t bh[4][2], bl[4][2];
            #pragma unroll
            for (int nt = 0; nt < 4; nt++) {
                int cn = wn + nt * 8 + gid;
                bh[nt][0] = Bh[(8 * s + cq    ) * BNP + cn];
                bh[nt][1] = Bh[(8 * s + cq + 4) * BNP + cn];
                bl[nt][0] = Bl[(8 * s + cq    ) * BNP + cn];
                bl[nt][1] = Bl[(8 * s + cq + 4) * BNP + cn];
            }
            #pragma unroll
            for (int mt = 0; mt < 4; mt++)
                #pragma unroll
                for (int nt = 0; nt < 4; nt++) {
                    mma_tf32(acc[mt][nt], ah[mt], bh[nt]);
                    mma_tf32(acc[mt][nt], ah[mt], bl[nt]);
                    mma_tf32(acc[mt][nt], al[mt], bh[nt]);
                }
        }
    }

    #pragma unroll
    for (int mt = 0; mt < 4; mt++) {
        int rlo = row0 + wm + mt * 16 + gid;
        int rhi = rlo + 8;
        #pragma unroll
        for (int nt = 0; nt < 4; nt++) {
            int cc = col0 + wn + nt * 8 + 2 * cq;
            if (rlo < M) {
                if (cc     < N) C[(size_t)rlo * ldc + cc    ] = acc[mt][nt][0];
                if (cc + 1 < N) C[(size_t)rlo * ldc + cc + 1] = acc[mt][nt][1];
            }
            if (rhi < M) {
                if (cc     < N) C[(size_t)rhi * ldc + cc    ] = acc[mt][nt][2];
                if (cc + 1 < N) C[(size_t)rhi * ldc + cc + 1] = acc[mt][nt][3];
            }
        }
    }
}

// ---------------------------------------------------------------------------
// adj_mma: per batch b, split-tf32 64x64 tile of dot = z @ x^T (+bias scalars)
// adj = dot^2 / max(rowsum(dot^2), 1e-12)
// ---------------------------------------------------------------------------
template<int NN>
__global__ __launch_bounds__(256, 2)
void adj_mma(const float* __restrict__ Z, int ldz,
             const float* __restrict__ X, int ldx,
             const float* __restrict__ r1, const float* __restrict__ r2,
             const float* __restrict__ cv, float* __restrict__ ADJ)
{
    __shared__ __align__(16) uint32_t sbuf[9728];
    __shared__ float r1s[64], r2s[64];
    uint32_t* qh = sbuf;
    uint32_t* ql = sbuf + 2560;
    uint32_t* kh = sbuf + 5120;
    uint32_t* kl = sbuf + 7424;

    const int b = blockIdx.x, tid = threadIdx.x;
    const int wid = tid >> 5, lane = tid & 31;
    const int gid = lane >> 2, cq = lane & 3;
    const int wm = (wid >> 2) * 32, wn = (wid & 3) * 16;

    if (tid < 64) {
        r1s[tid] = (tid < NN) ? r1[(size_t)b * NN + tid] : 0.f;
        r2s[tid] = (tid < NN) ? r2[(size_t)b * NN + tid] : 0.f;
    }
    const float c3 = cv[2 * NF];

    const float* q = Z + (size_t)b * NN * ldz;
    const float* k = X + (size_t)b * NN * ldx;

    float acc[2][2][4];
    #pragma unroll
    for (int a = 0; a < 2; a++)
        #pragma unroll
        for (int c = 0; c < 2; c++)
            #pragma unroll
            for (int e = 0; e < 4; e++) acc[a][c][e] = 0.f;

    for (int k0 = 0; k0 < NF; k0 += 32) {
        __syncthreads();
        #pragma unroll
        for (int i = 0; i < 2; i++) {
            int u = tid + i * 256;
            int m = u >> 3, kq = u & 7;
            float4 v = make_float4(0.f, 0.f, 0.f, 0.f);
            if (m < NN) v = *reinterpret_cast<const float4*>(q + (size_t)m * ldz + k0 + 4 * kq);
            int base = m * 40 + 8 * (kq >> 1) + (kq & 1);
            float xs[4] = {v.x, v.y, v.z, v.w};
            #pragma unroll
            for (int j = 0; j < 4; j++) {
                uint32_t hi = f2tf32(xs[j]);
                qh[base + 2 * j] = hi;
                ql[base + 2 * j] = f2tf32(xs[j] - __uint_as_float(hi));
            }
        }
        #pragma unroll
        for (int i = 0; i < 2; i++) {
            int u = tid + i * 256;
            int n = u >> 3, kq = u & 7;
            float4 v = make_float4(0.f, 0.f, 0.f, 0.f);
            if (n < NN) v = *reinterpret_cast<const float4*>(k + (size_t)n * ldx + k0 + 4 * kq);
            int base = n * 36 + 4 * kq;
            float xs[4] = {v.x, v.y, v.z, v.w};
            #pragma unroll
            for (int j = 0; j < 4; j++) {
                uint32_t hi = f2tf32(xs[j]);
                kh[base + j] = hi;
                kl[base + j] = f2tf32(xs[j] - __uint_as_float(hi));
            }
        }
        __syncthreads();

        #pragma unroll
        for (int s = 0; s < 4; s++) {
            uint32_t ah[2][4], al[2][4], bh[2][2], bl[2][2];
            #pragma unroll
            for (int mt = 0; mt < 2; mt++) {
                int r0 = wm + mt * 16 + gid;
                uint2 t0 = *reinterpret_cast<const uint2*>(&qh[(r0    ) * 40 + 8 * s + 2 * cq]);
                uint2 t1 = *reinterpret_cast<const uint2*>(&qh[(r0 + 8) * 40 + 8 * s + 2 * cq]);
                ah[mt][0] = t0.x; ah[mt][1] = t1.x; ah[mt][2] = t0.y; ah[mt][3] = t1.y;
                uint2 u0 = *reinterpret_cast<const uint2*>(&ql[(r0    ) * 40 + 8 * s + 2 * cq]);
                uint2 u1 = *reinterpret_cast<const uint2*>(&ql[(r0 + 8) * 40 + 8 * s + 2 * cq]);
                al[mt][0] = u0.x; al[mt][1] = u1.x; al[mt][2] = u0.y; al[mt][3] = u1.y;
            }
            #pragma unroll
            for (int nt = 0; nt < 2; nt++) {
                int n = wn + 8 * nt + gid;
                bh[nt][0] = kh[n * 36 + 8 * s + cq];
                bh[nt][1] = kh[n * 36 + 8 * s + cq + 4];
                bl[nt][0] = kl[n * 36 + 8 * s + cq];
                bl[nt][1] = kl[n * 36 + 8 * s + cq + 4];
            }
            #pragma unroll
            for (int mt = 0; mt < 2; mt++)
                #pragma unroll
                for (int nt = 0; nt < 2; nt++) {
                    mma_tf32(acc[mt][nt], ah[mt], bh[nt]);
                    mma_tf32(acc[mt][nt], ah[mt], bl[nt]);
                    mma_tf32(acc[mt][nt], al[mt], bh[nt]);
                }
        }
    }
    __syncthreads();

    float* sq   = reinterpret_cast<float*>(sbuf);
    float* rinv = reinterpret_cast<float*>(sbuf) + 4400;

    #pragma unroll
    for (int mt = 0; mt < 2; mt++)
        #pragma unroll
        for (int nt = 0; nt < 2; nt++) {
            int r = wm + 16 * mt + gid;
            int c = wn + 8 * nt + 2 * cq;
            float d0 = acc[mt][nt][0] + r1s[r    ] + r2s[c    ] + c3;
            float d1 = acc[mt][nt][1] + r1s[r    ] + r2s[c + 1] + c3;
            float d2 = acc[mt][nt][2] + r1s[r + 8] + r2s[c    ] + c3;
            float d3 = acc[mt][nt][3] + r1s[r + 8] + r2s[c + 1] + c3;
            sq[(r    ) * 68 + c    ] = (c     < NN) ? d0 * d0 : 0.f;
            sq[(r    ) * 68 + c + 1] = (c + 1 < NN) ? d1 * d1 : 0.f;
            sq[(r + 8) * 68 + c    ] = (c     < NN) ? d2 * d2 : 0.f;
            sq[(r + 8) * 68 + c + 1] = (c + 1 < NN) ? d3 * d3 : 0.f;
        }
    __syncthreads();

    for (int r = wid; r < NN; r += 8) {
        float s = sq[r * 68 + lane] + sq[r * 68 + 32 + lane];
        #pragma unroll
        for (int o = 16; o; o >>= 1) s += __shfl_xor_sync(0xffffffffu, s, o);
        if (lane == 0) rinv[r] = 1.f / fmaxf(s, 1e-12f);
    }
    __syncthreads();

    for (int idx = tid; idx < NN * NN; idx += 256) {
        int n = idx / NN, m = idx - n * NN;
        ADJ[(size_t)b * NN * NN + idx] = sq[n * 68 + m] * rinv[n];
    }
}

// ---------------------------------------------------------------------------
// Fused GCN layer (adj@xw + LN + ReLU [+ node mean]); 768 threads per batch.
// ---------------------------------------------------------------------------
template<int NN, bool MEAN>
__global__ __launch_bounds__(768, 1)
void gcn_fused(const float* __restrict__ ADJ, const float* __restrict__ XW, int ldxw,
               const float* __restrict__ g, const float* __restrict__ bb,
               float* __restrict__ OUT)
{
    extern __shared__ float sm[];
    float* adjs = sm;
    float* mu   = sm + NN * NN;
    float* rs   = mu + NN;
    float* h    = rs + NN;

    const int b = blockIdx.x;
    const int j = threadIdx.x;
    const int w = j >> 5, lane = j & 31;

    float xcol[NN];
    #pragma unroll
    for (int m = 0; m < NN; m++)
        xcol[m] = XW[((size_t)b * NN + m) * ldxw + j];

    for (int idx = j; idx < NN * NN; idx += 768)
        adjs[idx] = ADJ[(size_t)b * NN * NN + idx];
    __syncthreads();

    for (int n = 0; n < NN; n++) {
        float s = 0.f;
        #pragma unroll
        for (int m = 0; m < NN; m++)
            s += adjs[n * NN + m] * xcol[m];
        h[n * NF + j] = s;
    }
    __syncthreads();

    for (int r = w; r < NN; r += 24) {
        float s = 0.f, ss = 0.f;
        #pragma unroll
        for (int c = lane; c < NF; c += 32) {
            float v = h[r * NF + c];
            s += v; ss += v * v;
        }
        #pragma unroll
        for (int o = 16; o; o >>= 1) {
            s  += __shfl_xor_sync(0xffffffffu, s, o);
            ss += __shfl_xor_sync(0xffffffffu, ss, o);
        }
        if (lane == 0) {
            float m_ = s * (1.f / NF);
            mu[r] = m_;
            rs[r] = rsqrtf(ss * (1.f / NF) - m_ * m_ + 1e-5f);
        }
    }
    __syncthreads();

    const float gg = g[j], bv = bb[j];
    if (MEAN) {
        float macc = 0.f;
        for (int n = 0; n < NN; n++) {
            float v = (h[n * NF + j] - mu[n]) * rs[n] * gg + bv;
            macc += fmaxf(v, 0.f);
        }
        OUT[(size_t)b * NF + j] = macc * (1.f / NN);
    } else {
        for (int n = 0; n < NN; n++) {
            float v = (h[n * NF + j] - mu[n]) * rs[n] * gg + bv;
            OUT[((size_t)b * NN + n) * NF + j] = fmaxf(v, 0.f);
        }
    }
}

// ---------------------------------------------------------------------------
// Prep kernels
// ---------------------------------------------------------------------------
__global__ void transpose_kernel(const float* __restrict__ in, float* __restrict__ out,
                                 int R, int C, int ldo, int col_off)
{
    __shared__ float t[32][33];
    int bx = blockIdx.x * 32, by = blockIdx.y * 32;
    int x = bx + threadIdx.x;
    for (int i = threadIdx.y; i < 32; i += 8) {
        int y = by + i;
        t[i][threadIdx.x] = (y < R && x < C) ? in[(size_t)y * C + x] : 0.f;
    }
    __syncthreads();
    int ox = by + threadIdx.x;
    for (int i = threadIdx.y; i < 32; i += 8) {
        int oy = bx + i;
        if (oy < C && ox < R) out[(size_t)oy * ldo + col_off + ox] = t[threadIdx.x][i];
    }
}

__global__ void copy_w0_kernel(const float* __restrict__ w0, float* __restrict__ wcomb)
{
    int k = blockIdx.x;
    for (int n = threadIdx.x; n < NF; n += 256)
        wcomb[(size_t)k * NZW + NF + n] = w0[(size_t)k * NF + n];
}

// c1 = wq^T @ bk (d<768), c2 = wk^T @ bq (d in [768,1536))
__global__ void cvec_kernel(const float* __restrict__ wq, const float* __restrict__ wk,
                            const float* __restrict__ bq, const float* __restrict__ bk,
                            float* __restrict__ cv)
{
    int d = blockIdx.x * 256 + threadIdx.x;
    if (d < NF) {
        float s = 0.f;
        for (int i = 0; i < NF; i++) s += wq[(size_t)i * NF + d] * bk[i];
        cv[d] = s;
    } else if (d < 2 * NF) {
        int e = d - NF;
        float s = 0.f;
        for (int i = 0; i < NF; i++) s += wk[(size_t)i * NF + e] * bq[i];
        cv[d] = s;
    }
}

__global__ void c3_kernel(const float* __restrict__ bq, const float* __restrict__ bk,
                          float* __restrict__ cv)
{
    __shared__ float red[8];
    int tid = threadIdx.x;
    float s = 0.f;
    for (int i = tid; i < NF; i += 256) s += bq[i] * bk[i];
    #pragma unroll
    for (int o = 16; o; o >>= 1) s += __shfl_xor_sync(0xffffffffu, s, o);
    if ((tid & 31) == 0) red[tid >> 5] = s;
    __syncthreads();
    if (tid == 0) {
        float t = 0.f;
        #pragma unroll
        for (int i = 0; i < 8; i++) t += red[i];
        cv[2 * NF] = t;
    }
}

// r1[row] = x[row]·c1, r2[row] = x[row]·c2 ; warp per row
__global__ void r12_kernel(const float* __restrict__ X, int ldx, int Mrows,
                           const float* __restrict__ cv,
                           float* __restrict__ r1, float* __restrict__ r2)
{
    int row  = blockIdx.x * 8 + (threadIdx.x >> 5);
    int lane = threadIdx.x & 31;
    if (row >= Mrows) return;
    const float* x = X + (size_t)row * ldx;
    float s1 = 0.f, s2 = 0.f;
    for (int j = lane; j < NF; j += 32) {
        float v = x[j];
        s1 += v * cv[j];
        s2 += v * cv[NF + j];
    }
    #pragma unroll
    for (int o = 16; o; o >>= 1) {
        s1 += __shfl_xor_sync(0xffffffffu, s1, o);
        s2 += __shfl_xor_sync(0xffffffffu, s2, o);
    }
    if (lane == 0) { r1[row] = s1; r2[row] = s2; }
}

__global__ void concat_kernel(const float* __restrict__ a, const float* __restrict__ g2,
                              float* __restrict__ y, int d)
{
    const int i = blockIdx.x;
    for (int jj = threadIdx.x; jj < d; jj += 256) {
        y[(size_t)i * 2 * d + jj]     = a[(size_t)i * d + jj];
        y[(size_t)i * 2 * d + d + jj] = g2[(size_t)i * d + jj];
    }
}

// ---------------------------------------------------------------------------
// Host side
// ---------------------------------------------------------------------------
static inline dim3 gemm_grid(int M, int N) {
    return dim3((N + 127) / 128, (M + 127) / 128);
}

template<int NN>
static void run_graph(const float* x_in, int Bt,
                      const float* wcomb, const float* cv,
                      const float* gcn_w, const float* ln_g, const float* ln_b,
                      float* p_zxw, float* p_xw, float* p_x, float* p_adj,
                      float* p_r1, float* p_r2, float* out_mean, size_t sm_fused)
{
    const int M = Bt * NN;
    // combined z|xw projection: [M,768] @ [768,1536]
    gemm_tf32<false><<<gemm_grid(M, NZW), 256, GEMM_SMEM>>>(
        x_in, wcomb, nullptr, p_zxw, M, NZW, NF, NF, NZW, NZW);
    r12_kernel<<<(M + 7) / 8, 256>>>(x_in, NF, M, cv, p_r1, p_r2);
    adj_mma<NN><<<Bt, 256>>>(p_zxw, NZW, x_in, NF, p_r1, p_r2, cv, p_adj);
    gcn_fused<NN, false><<<Bt, 768, sm_fused>>>(p_adj, p_zxw + NF, NZW, ln_g, ln_b, p_x);
    gemm_tf32<false><<<gemm_grid(M, NF), 256, GEMM_SMEM>>>(
        p_x, gcn_w + (size_t)NF * NF, nullptr, p_xw, M, NF, NF, NF, NF, NF);
    gcn_fused<NN, true><<<Bt, 768, sm_fused>>>(p_adj, p_xw, NF, ln_g + NF, ln_b + NF, out_mean);
}

extern "C" void kernel_launch(void* const* d_in, const int* in_sizes, int n_in,
                              void* d_out, int out_size)
{
    const float* feats  = (const float*)d_in[0];
    const float* fglob  = (const float*)d_in[1];
    const float* wq_w   = (const float*)d_in[3];
    const float* wq_b   = (const float*)d_in[4];
    const float* wk_w   = (const float*)d_in[5];
    const float* wk_b   = (const float*)d_in[6];
    const float* gcn_w  = (const float*)d_in[7];
    const float* ln_g   = (const float*)d_in[8];
    const float* ln_b   = (const float*)d_in[9];
    const float* fc1_w  = (const float*)d_in[10];
    const float* fc1_b  = (const float*)d_in[11];
    const float* fc2_w  = (const float*)d_in[12];
    const float* fc2_b  = (const float*)d_in[13];
    float* out = (float*)d_out;

    float *p_zxw, *p_xw, *p_x, *p_adj, *p_mean, *p_mean2, *p_hc;
    float *p_wcomb, *p_wqT, *p_fc1T, *p_fc2T, *p_cv, *p_r1, *p_r2;
    cudaGetSymbolAddress((void**)&p_zxw,  g_zxw);
    cudaGetSymbolAddress((void**)&p_xw,   g_xw);
    cudaGetSymbolAddress((void**)&p_x,    g_x);
    cudaGetSymbolAddress((void**)&p_adj,  g_adj);
    cudaGetSymbolAddress((void**)&p_mean, g_mean);
    cudaGetSymbolAddress((void**)&p_mean2,g_mean2);
    cudaGetSymbolAddress((void**)&p_hc,   g_hc);
    cudaGetSymbolAddress((void**)&p_wcomb,g_wcomb);
    cudaGetSymbolAddress((void**)&p_wqT,  g_wqT);
    cudaGetSymbolAddress((void**)&p_fc1T, g_fc1T);
    cudaGetSymbolAddress((void**)&p_fc2T, g_fc2T);
    cudaGetSymbolAddress((void**)&p_cv,   g_cvec);
    cudaGetSymbolAddress((void**)&p_r1,   g_r1);
    cudaGetSymbolAddress((void**)&p_r2,   g_r2);

    const size_t sm50 = (size_t)(NN1 * NN1 + 2 * NN1 + NN1 * NF) * 4;
    const size_t sm32 = (size_t)(NN2 * NN2 + 2 * NN2 + NN2 * NF) * 4;
    cudaFuncSetAttribute(gcn_fused<NN1, false>, cudaFuncAttributeMaxDynamicSharedMemorySize, (int)sm50);
    cudaFuncSetAttribute(gcn_fused<NN1, true >, cudaFuncAttributeMaxDynamicSharedMemorySize, (int)sm50);
    cudaFuncSetAttribute(gcn_fused<NN2, false>, cudaFuncAttributeMaxDynamicSharedMemorySize, (int)sm32);
    cudaFuncSetAttribute(gcn_fused<NN2, true >, cudaFuncAttributeMaxDynamicSharedMemorySize, (int)sm32);
    cudaFuncSetAttribute(gemm_tf32<false>, cudaFuncAttributeMaxDynamicSharedMemorySize, GEMM_SMEM);
    cudaFuncSetAttribute(gemm_tf32<true >, cudaFuncAttributeMaxDynamicSharedMemorySize, GEMM_SMEM);
    cudaFuncSetAttribute(gemm_split,       cudaFuncAttributeMaxDynamicSharedMemorySize, GEMM_SMEM);

    // ---- prep: A = wq^T @ wk (split-tf32, fp32-accurate), W0 copy, bias vecs ----
    dim3 tb(32, 8);
    transpose_kernel<<<dim3(NF / 32, NF / 32), tb>>>(wq_w, p_wqT, NF, NF, NF, 0);
    gemm_split<<<gemm_grid(NF, NF), 256, GEMM_SMEM>>>(
        p_wqT, wk_w, p_wcomb, NF, NF, NF, NF, NF, NZW);
    copy_w0_kernel<<<NF, 256>>>(gcn_w, p_wcomb);
    cvec_kernel<<<6, 256>>>(wq_w, wk_w, wq_b, wk_b, p_cv);
    c3_kernel<<<1, 256>>>(wq_b, wk_b, p_cv);
    transpose_kernel<<<dim3(NF2 / 32, NF / 32), tb>>>(fc1_w, p_fc1T, NF, NF2, NF, 0);
    transpose_kernel<<<dim3(NF / 32, (NC + 31) / 32), tb>>>(fc2_w, p_fc2T, NC, NF, NC, 0);

    // ---- graph pass 1: [512, 50, 768] -> [512, 768] ----
    run_graph<NN1>(feats, NB1, p_wcomb, p_cv, gcn_w, ln_g, ln_b,
                   p_zxw, p_xw, p_x, p_adj, p_r1, p_r2, p_mean, sm50);

    // ---- graph pass 2: [16, 32, 768] -> [16, 768] ----
    run_graph<NN2>(p_mean, NB2, p_wcomb, p_cv, gcn_w, ln_g, ln_b,
                   p_zxw, p_xw, p_x, p_adj, p_r1, p_r2, p_mean2, sm32);

    // ---- classifier ----
    float* y_out = out + NB2 * NC;
    concat_kernel<<<NB2, 256>>>(p_mean2, fglob, y_out, NF);
    gemm_tf32<true ><<<gemm_grid(NB2, NF), 256, GEMM_SMEM>>>(
        y_out, p_fc1T, fc1_b, p_hc, NB2, NF, NF2, NF2, NF, NF);
    gemm_tf32<false><<<gemm_grid(NB2, NC), 256, GEMM_SMEM>>>(
        p_hc, p_fc2T, fc2_b, out, NB2, NC, NF, NF, NC, NC);
}

// round 5
// speedup vs baseline: 4.1197x; 1.1028x over previous
#include <cuda_runtime.h>
#include <cstdint>

// ---------------------------------------------------------------------------
// Problem constants
// ---------------------------------------------------------------------------
#define NF   768
#define NB1  512
#define NN1  50
#define NB2  16
#define NN2  32
#define M1   (NB1*NN1)    // 25600
#define NC   400
#define NF2  (2*NF)
#define NZW  1536         // combined z|xw width

// ---------------------------------------------------------------------------
// Scratch (device globals)
// ---------------------------------------------------------------------------
__device__ float g_zxw [(size_t)M1 * NZW];    // z | xw, ld=1536
__device__ float g_xw  [(size_t)M1 * NF];
__device__ float g_x   [(size_t)M1 * NF];
__device__ float g_adj [(size_t)NB1 * NN1 * NN1];
__device__ float g_mean[(size_t)NB1 * NF];
__device__ float g_mean2[(size_t)NB2 * NF];
__device__ float g_hc  [(size_t)NB2 * NF];
__device__ float g_wcomb[(size_t)NF * NZW];   // [K=768][N=1536]: A | W0
__device__ float g_wqT [(size_t)NF * NF];
__device__ float g_cvec[2 * NF + 1];          // c1 | c2 | c3
__device__ float g_cpart[8 * 2 * NF];

// ---------------------------------------------------------------------------
// tf32 / f32x2 helpers
// ---------------------------------------------------------------------------
__device__ __forceinline__ uint32_t f2tf32(float f) {
    uint32_t r;
    asm("cvt.rna.tf32.f32 %0, %1;" : "=r"(r) : "f"(f));
    return r;
}

__device__ __forceinline__ void mma_tf32(float* d, const uint32_t* a, const uint32_t* b) {
    asm volatile(
        "mma.sync.aligned.m16n8k8.row.col.f32.tf32.tf32.f32 "
        "{%0,%1,%2,%3}, {%4,%5,%6,%7}, {%8,%9}, {%0,%1,%2,%3};"
        : "+f"(d[0]), "+f"(d[1]), "+f"(d[2]), "+f"(d[3])
        : "r"(a[0]), "r"(a[1]), "r"(a[2]), "r"(a[3]), "r"(b[0]), "r"(b[1]));
}

__device__ __forceinline__ unsigned long long fma_f32x2(
    unsigned long long a, unsigned long long b, unsigned long long c) {
    unsigned long long d;
    asm("fma.rn.f32x2 %0, %1, %2, %3;" : "=l"(d) : "l"(a), "l"(b), "l"(c));
    return d;
}

__device__ __forceinline__ unsigned long long pack_f32x2(float lo, float hi) {
    unsigned long long p;
    asm("mov.b64 %0, {%1, %2};" : "=l"(p) : "f"(lo), "f"(hi));
    return p;
}

__device__ __forceinline__ void unpack_f32x2(unsigned long long p, float& lo, float& hi) {
    asm("mov.b64 {%0, %1}, %2;" : "=f"(lo), "=f"(hi) : "l"(p));
}

// ---------------------------------------------------------------------------
// Pipelined TF32 GEMM: C = A[M,K] @ B[K,N], 128x128x32, 256 thr, dbl-buffer.
// ---------------------------------------------------------------------------
#define GEMM_SMEM 74752

__global__ __launch_bounds__(256, 2)
void gemm_tf32(const float* __restrict__ A, const float* __restrict__ B,
               float* __restrict__ C, int M, int N, int K,
               int lda, int ldb, int ldc)
{
    constexpr int BK = 32, AKP = 40, BNP = 132;
    constexpr int ASZ = 128 * AKP, BSZ = BK * BNP;
    extern __shared__ uint32_t smg[];

    const int tid  = threadIdx.x;
    const int wid  = tid >> 5, lane = tid & 31;
    const int gid  = lane >> 2, cq = lane & 3;
    const int wm   = (wid >> 2) * 64, wn = (wid & 3) * 32;
    const int row0 = blockIdx.y * 128, col0 = blockIdx.x * 128;
    const int NK   = K / BK;

    float acc[4][4][4];
    #pragma unroll
    for (int i = 0; i < 4; i++)
        #pragma unroll
        for (int j = 0; j < 4; j++)
            #pragma unroll
            for (int q = 0; q < 4; q++) acc[i][j][q] = 0.f;

    float4 rA[4];
    #pragma unroll
    for (int i = 0; i < 4; i++) {
        int u = tid + i * 256, m = u >> 3, kq = u & 7;
        int gm = row0 + m;
        rA[i] = (gm < M) ? *reinterpret_cast<const float4*>(A + (size_t)gm * lda + 4 * kq)
                         : make_float4(0.f, 0.f, 0.f, 0.f);
    }

    for (int it = 0; it < NK; it++) {
        const int p = it & 1;
        uint32_t* Ap = smg + p * ASZ;
        uint32_t* Bp = smg + 2 * ASZ + p * BSZ;

        #pragma unroll
        for (int i = 0; i < 4; i++) {
            int u = tid + i * 256, m = u >> 3, kq = u & 7;
            int base = m * AKP + 8 * (kq >> 1) + (kq & 1);
            Ap[base + 0] = f2tf32(rA[i].x);
            Ap[base + 2] = f2tf32(rA[i].y);
            Ap[base + 4] = f2tf32(rA[i].z);
            Ap[base + 6] = f2tf32(rA[i].w);
        }
        #pragma unroll
        for (int i = 0; i < 4; i++) {
            int u = tid + i * 256, k = u >> 5, nq = u & 31;
            int gn = col0 + 4 * nq;
            const float* bp = B + (size_t)(it * BK + k) * ldb + gn;
            float x0 = (gn + 0 < N) ? bp[0] : 0.f;
            float x1 = (gn + 1 < N) ? bp[1] : 0.f;
            float x2 = (gn + 2 < N) ? bp[2] : 0.f;
            float x3 = (gn + 3 < N) ? bp[3] : 0.f;
            int base = k * BNP + 4 * nq;
            Bp[base + 0] = f2tf32(x0);
            Bp[base + 1] = f2tf32(x1);
            Bp[base + 2] = f2tf32(x2);
            Bp[base + 3] = f2tf32(x3);
        }
        if (it + 1 < NK) {
            #pragma unroll
            for (int i = 0; i < 4; i++) {
                int u = tid + i * 256, m = u >> 3, kq = u & 7;
                int gm = row0 + m;
                rA[i] = (gm < M)
                    ? *reinterpret_cast<const float4*>(A + (size_t)gm * lda + (it + 1) * BK + 4 * kq)
                    : make_float4(0.f, 0.f, 0.f, 0.f);
            }
        }
        __syncthreads();

        #pragma unroll
        for (int s = 0; s < 4; s++) {
            uint32_t af[4][4];
            #pragma unroll
            for (int mt = 0; mt < 4; mt++) {
                int r0 = wm + mt * 16 + gid;
                uint2 t0 = *reinterpret_cast<const uint2*>(&Ap[(r0    ) * AKP + 8 * s + 2 * cq]);
                uint2 t1 = *reinterpret_cast<const uint2*>(&Ap[(r0 + 8) * AKP + 8 * s + 2 * cq]);
                af[mt][0] = t0.x; af[mt][1] = t1.x; af[mt][2] = t0.y; af[mt][3] = t1.y;
            }
            uint32_t bf[4][2];
            #pragma unroll
            for (int nt = 0; nt < 4; nt++) {
                int cn = wn + nt * 8 + gid;
                bf[nt][0] = Bp[(8 * s + cq    ) * BNP + cn];
                bf[nt][1] = Bp[(8 * s + cq + 4) * BNP + cn];
            }
            #pragma unroll
            for (int mt = 0; mt < 4; mt++)
                #pragma unroll
                for (int nt = 0; nt < 4; nt++)
                    mma_tf32(acc[mt][nt], af[mt], bf[nt]);
        }
    }

    #pragma unroll
    for (int mt = 0; mt < 4; mt++) {
        int rlo = row0 + wm + mt * 16 + gid;
        int rhi = rlo + 8;
        #pragma unroll
        for (int nt = 0; nt < 4; nt++) {
            int cc = col0 + wn + nt * 8 + 2 * cq;
            if (rlo < M) {
                if (cc     < N) C[(size_t)rlo * ldc + cc    ] = acc[mt][nt][0];
                if (cc + 1 < N) C[(size_t)rlo * ldc + cc + 1] = acc[mt][nt][1];
            }
            if (rhi < M) {
                if (cc     < N) C[(size_t)rhi * ldc + cc    ] = acc[mt][nt][2];
                if (cc + 1 < N) C[(size_t)rhi * ldc + cc + 1] = acc[mt][nt][3];
            }
        }
    }
}

// ---------------------------------------------------------------------------
// Split-tf32 GEMM (fp32-accurate), single-buffer; for A = wqT @ wk.
// ---------------------------------------------------------------------------
__global__ __launch_bounds__(256, 1)
void gemm_split(const float* __restrict__ A, const float* __restrict__ B,
                float* __restrict__ C, int M, int N, int K,
                int lda, int ldb, int ldc)
{
    constexpr int BK = 32, AKP = 40, BNP = 132;
    constexpr int ASZ = 128 * AKP, BSZ = BK * BNP;
    extern __shared__ uint32_t smg[];
    uint32_t* Ah = smg;
    uint32_t* Al = smg + ASZ;
    uint32_t* Bh = smg + 2 * ASZ;
    uint32_t* Bl = smg + 2 * ASZ + BSZ;

    const int tid  = threadIdx.x;
    const int wid  = tid >> 5, lane = tid & 31;
    const int gid  = lane >> 2, cq = lane & 3;
    const int wm   = (wid >> 2) * 64, wn = (wid & 3) * 32;
    const int row0 = blockIdx.y * 128, col0 = blockIdx.x * 128;

    float acc[4][4][4];
    #pragma unroll
    for (int i = 0; i < 4; i++)
        #pragma unroll
        for (int j = 0; j < 4; j++)
            #pragma unroll
            for (int q = 0; q < 4; q++) acc[i][j][q] = 0.f;

    for (int k0 = 0; k0 < K; k0 += BK) {
        __syncthreads();
        #pragma unroll
        for (int i = 0; i < 4; i++) {
            int u = tid + i * 256, m = u >> 3, kq = u & 7;
            int gm = row0 + m;
            float4 v = (gm < M) ? *reinterpret_cast<const float4*>(A + (size_t)gm * lda + k0 + 4 * kq)
                                : make_float4(0.f, 0.f, 0.f, 0.f);
            int base = m * AKP + 8 * (kq >> 1) + (kq & 1);
            float xs[4] = {v.x, v.y, v.z, v.w};
            #pragma unroll
            for (int j = 0; j < 4; j++) {
                uint32_t hi = f2tf32(xs[j]);
                Ah[base + 2 * j] = hi;
                Al[base + 2 * j] = f2tf32(xs[j] - __uint_as_float(hi));
            }
        }
        #pragma unroll
        for (int i = 0; i < 4; i++) {
            int u = tid + i * 256, k = u >> 5, nq = u & 31;
            int gn = col0 + 4 * nq;
            const float* bp = B + (size_t)(k0 + k) * ldb + gn;
            int base = k * BNP + 4 * nq;
            #pragma unroll
            for (int j = 0; j < 4; j++) {
                float x = (gn + j < N) ? bp[j] : 0.f;
                uint32_t hi = f2tf32(x);
                Bh[base + j] = hi;
                Bl[base + j] = f2tf32(x - __uint_as_float(hi));
            }
        }
        __syncthreads();

        #pragma unroll
        for (int s = 0; s < 4; s++) {
            uint32_t ah[4][4], al[4][4];
            #pragma unroll
            for (int mt = 0; mt < 4; mt++) {
                int r0 = wm + mt * 16 + gid;
                uint2 t0 = *reinterpret_cast<const uint2*>(&Ah[(r0    ) * AKP + 8 * s + 2 * cq]);
                uint2 t1 = *reinterpret_cast<const uint2*>(&Ah[(r0 + 8) * AKP + 8 * s + 2 * cq]);
                ah[mt][0] = t0.x; ah[mt][1] = t1.x; ah[mt][2] = t0.y; ah[mt][3] = t1.y;
                uint2 u0 = *reinterpret_cast<const uint2*>(&Al[(r0    ) * AKP + 8 * s + 2 * cq]);
                uint2 u1 = *reinterpret_cast<const uint2*>(&Al[(r0 + 8) * AKP + 8 * s + 2 * cq]);
                al[mt][0] = u0.x; al[mt][1] = u1.x; al[mt][2] = u0.y; al[mt][3] = u1.y;
            }
            uint32_t bh[4][2], bl[4][2];
            #pragma unroll
            for (int nt = 0; nt < 4; nt++) {
                int cn = wn + nt * 8 + gid;
                bh[nt][0] = Bh[(8 * s + cq    ) * BNP + cn];
                bh[nt][1] = Bh[(8 * s + cq + 4) * BNP + cn];
                bl[nt][0] = Bl[(8 * s + cq    ) * BNP + cn];
                bl[nt][1] = Bl[(8 * s + cq + 4) * BNP + cn];
            }
            #pragma unroll
            for (int mt = 0; mt < 4; mt++)
                #pragma unroll
                for (int nt = 0; nt < 4; nt++) {
                    mma_tf32(acc[mt][nt], ah[mt], bh[nt]);
                    mma_tf32(acc[mt][nt], ah[mt], bl[nt]);
                    mma_tf32(acc[mt][nt], al[mt], bh[nt]);
                }
        }
    }

    #pragma unroll
    for (int mt = 0; mt < 4; mt++) {
        int rlo = row0 + wm + mt * 16 + gid;
        int rhi = rlo + 8;
        #pragma unroll
        for (int nt = 0; nt < 4; nt++) {
            int cc = col0 + wn + nt * 8 + 2 * cq;
            if (rlo < M) {
                if (cc     < N) C[(size_t)rlo * ldc + cc    ] = acc[mt][nt][0];
                if (cc + 1 < N) C[(size_t)rlo * ldc + cc + 1] = acc[mt][nt][1];
            }
            if (rhi < M) {
                if (cc     < N) C[(size_t)rhi * ldc + cc    ] = acc[mt][nt][2];
                if (cc + 1 < N) C[(size_t)rhi * ldc + cc + 1] = acc[mt][nt][3];
            }
        }
    }
}

// ---------------------------------------------------------------------------
// adj_mma: per batch b, split-tf32 dot = z @ x^T; r1/r2 computed in-kernel
// from the staged x (hi+lo reconstruction) dotted with c1/c2.
// adj = dot^2 / max(rowsum(dot^2), 1e-12)
// ---------------------------------------------------------------------------
template<int NN>
__global__ __launch_bounds__(256, 2)
void adj_mma(const float* __restrict__ Z, int ldz,
             const float* __restrict__ X, int ldx,
             const float* __restrict__ cv, float* __restrict__ ADJ)
{
    __shared__ __align__(16) uint32_t sbuf[9728];
    __shared__ float r1s[64], r2s[64];
    uint32_t* qh = sbuf;
    uint32_t* ql = sbuf + 2560;
    uint32_t* kh = sbuf + 5120;
    uint32_t* kl = sbuf + 7424;

    const int b = blockIdx.x, tid = threadIdx.x;
    const int wid = tid >> 5, lane = tid & 31;
    const int gid = lane >> 2, cq = lane & 3;
    const int wm = (wid >> 2) * 32, wn = (wid & 3) * 16;

    const float c3 = cv[2 * NF];
    const int rn = tid >> 2;          // row for r12 (0..63)
    const int rq = tid & 3;           // k quarter

    const float* q = Z + (size_t)b * NN * ldz;
    const float* k = X + (size_t)b * NN * ldx;

    float acc[2][2][4];
    #pragma unroll
    for (int a = 0; a < 2; a++)
        #pragma unroll
        for (int c = 0; c < 2; c++)
            #pragma unroll
            for (int e = 0; e < 4; e++) acc[a][c][e] = 0.f;

    float racc1 = 0.f, racc2 = 0.f;

    for (int k0 = 0; k0 < NF; k0 += 32) {
        __syncthreads();
        #pragma unroll
        for (int i = 0; i < 2; i++) {
            int u = tid + i * 256;
            int m = u >> 3, kq = u & 7;
            float4 v = make_float4(0.f, 0.f, 0.f, 0.f);
            if (m < NN) v = *reinterpret_cast<const float4*>(q + (size_t)m * ldz + k0 + 4 * kq);
            int base = m * 40 + 8 * (kq >> 1) + (kq & 1);
            float xs[4] = {v.x, v.y, v.z, v.w};
            #pragma unroll
            for (int j = 0; j < 4; j++) {
                uint32_t hi = f2tf32(xs[j]);
                qh[base + 2 * j] = hi;
                ql[base + 2 * j] = f2tf32(xs[j] - __uint_as_float(hi));
            }
        }
        #pragma unroll
        for (int i = 0; i < 2; i++) {
            int u = tid + i * 256;
            int n = u >> 3, kq = u & 7;
            float4 v = make_float4(0.f, 0.f, 0.f, 0.f);
            if (n < NN) v = *reinterpret_cast<const float4*>(k + (size_t)n * ldx + k0 + 4 * kq);
            int base = n * 36 + 4 * kq;
            float xs[4] = {v.x, v.y, v.z, v.w};
            #pragma unroll
            for (int j = 0; j < 4; j++) {
                uint32_t hi = f2tf32(xs[j]);
                kh[base + j] = hi;
                kl[base + j] = f2tf32(xs[j] - __uint_as_float(hi));
            }
        }
        __syncthreads();

        // r1/r2 partial dots from staged x (hi+lo)
        {
            const uint32_t* khp = &kh[rn * 36 + rq * 8];
            const uint32_t* klp = &kl[rn * 36 + rq * 8];
            const float* c1p = cv + k0 + rq * 8;
            const float* c2p = cv + NF + k0 + rq * 8;
            #pragma unroll
            for (int kk = 0; kk < 8; kk++) {
                float xm = __uint_as_float(khp[kk]) + __uint_as_float(klp[kk]);
                racc1 += xm * c1p[kk];
                racc2 += xm * c2p[kk];
            }
        }

        #pragma unroll
        for (int s = 0; s < 4; s++) {
            uint32_t ah[2][4], al[2][4], bh[2][2], bl[2][2];
            #pragma unroll
            for (int mt = 0; mt < 2; mt++) {
                int r0 = wm + mt * 16 + gid;
                uint2 t0 = *reinterpret_cast<const uint2*>(&qh[(r0    ) * 40 + 8 * s + 2 * cq]);
                uint2 t1 = *reinterpret_cast<const uint2*>(&qh[(r0 + 8) * 40 + 8 * s + 2 * cq]);
                ah[mt][0] = t0.x; ah[mt][1] = t1.x; ah[mt][2] = t0.y; ah[mt][3] = t1.y;
                uint2 u0 = *reinterpret_cast<const uint2*>(&ql[(r0    ) * 40 + 8 * s + 2 * cq]);
                uint2 u1 = *reinterpret_cast<const uint2*>(&ql[(r0 + 8) * 40 + 8 * s + 2 * cq]);
                al[mt][0] = u0.x; al[mt][1] = u1.x; al[mt][2] = u0.y; al[mt][3] = u1.y;
            }
            #pragma unroll
            for (int nt = 0; nt < 2; nt++) {
                int n = wn + 8 * nt + gid;
                bh[nt][0] = kh[n * 36 + 8 * s + cq];
                bh[nt][1] = kh[n * 36 + 8 * s + cq + 4];
                bl[nt][0] = kl[n * 36 + 8 * s + cq];
                bl[nt][1] = kl[n * 36 + 8 * s + cq + 4];
            }
            #pragma unroll
            for (int mt = 0; mt < 2; mt++)
                #pragma unroll
                for (int nt = 0; nt < 2; nt++) {
                    mma_tf32(acc[mt][nt], ah[mt], bh[nt]);
                    mma_tf32(acc[mt][nt], ah[mt], bl[nt]);
                    mma_tf32(acc[mt][nt], al[mt], bh[nt]);
                }
        }
    }

    // reduce r1/r2 over the 4-thread quartets (lanes 4n..4n+3 share rn)
    #pragma unroll
    for (int o = 1; o <= 2; o <<= 1) {
        racc1 += __shfl_xor_sync(0xffffffffu, racc1, o);
        racc2 += __shfl_xor_sync(0xffffffffu, racc2, o);
    }
    if (rq == 0) { r1s[rn] = racc1; r2s[rn] = racc2; }
    __syncthreads();

    float* sq   = reinterpret_cast<float*>(sbuf);
    float* rinv = reinterpret_cast<float*>(sbuf) + 4400;

    #pragma unroll
    for (int mt = 0; mt < 2; mt++)
        #pragma unroll
        for (int nt = 0; nt < 2; nt++) {
            int r = wm + 16 * mt + gid;
            int c = wn + 8 * nt + 2 * cq;
            float d0 = acc[mt][nt][0] + r1s[r    ] + r2s[c    ] + c3;
            float d1 = acc[mt][nt][1] + r1s[r    ] + r2s[c + 1] + c3;
            float d2 = acc[mt][nt][2] + r1s[r + 8] + r2s[c    ] + c3;
            float d3 = acc[mt][nt][3] + r1s[r + 8] + r2s[c + 1] + c3;
            sq[(r    ) * 68 + c    ] = (c     < NN) ? d0 * d0 : 0.f;
            sq[(r    ) * 68 + c + 1] = (c + 1 < NN) ? d1 * d1 : 0.f;
            sq[(r + 8) * 68 + c    ] = (c     < NN) ? d2 * d2 : 0.f;
            sq[(r + 8) * 68 + c + 1] = (c + 1 < NN) ? d3 * d3 : 0.f;
        }
    __syncthreads();

    for (int r = wid; r < NN; r += 8) {
        float s = sq[r * 68 + lane] + sq[r * 68 + 32 + lane];
        #pragma unroll
        for (int o = 16; o; o >>= 1) s += __shfl_xor_sync(0xffffffffu, s, o);
        if (lane == 0) rinv[r] = 1.f / fmaxf(s, 1e-12f);
    }
    __syncthreads();

    for (int idx = tid; idx < NN * NN; idx += 256) {
        int n = idx / NN, m = idx - n * NN;
        ADJ[(size_t)b * NN * NN + idx] = sq[n * 68 + m] * rinv[n];
    }
}

// ---------------------------------------------------------------------------
// Fused GCN layer with packed f32x2 FMA over node-pairs:
//   h = adj @ xw ; x = relu(LN(h)*g+b) [; node-mean]
// ---------------------------------------------------------------------------
template<int NN, bool MEAN>
__global__ __launch_bounds__(768, 1)
void gcn_fused(const float* __restrict__ ADJ, const float* __restrict__ XW, int ldxw,
               const float* __restrict__ g, const float* __restrict__ bb,
               float* __restrict__ OUT)
{
    constexpr int NP = NN / 2;
    extern __shared__ float sm[];
    float* adjs = sm;                    // [NN*NN], 8B-aligned rows (NN even)
    float* mu   = sm + NN * NN;
    float* rs   = mu + NN;
    float* h    = rs + NN;

    const int b = blockIdx.x;
    const int j = threadIdx.x;
    const int w = j >> 5, lane = j & 31;

    // xw column j, packed as consecutive-node pairs
    unsigned long long xc2[NP];
    #pragma unroll
    for (int mi = 0; mi < NP; mi++) {
        float x0 = XW[((size_t)b * NN + 2 * mi    ) * ldxw + j];
        float x1 = XW[((size_t)b * NN + 2 * mi + 1) * ldxw + j];
        xc2[mi] = pack_f32x2(x0, x1);
    }

    for (int idx = j; idx < NN * NN; idx += 768)
        adjs[idx] = ADJ[(size_t)b * NN * NN + idx];
    __syncthreads();

    for (int n = 0; n < NN; n++) {
        const unsigned long long* arow =
            reinterpret_cast<const unsigned long long*>(&adjs[n * NN]);
        unsigned long long a2 = 0ull;   // {0.f, 0.f}
        #pragma unroll
        for (int mi = 0; mi < NP; mi++)
            a2 = fma_f32x2(arow[mi], xc2[mi], a2);
        float lo, hi;
        unpack_f32x2(a2, lo, hi);
        h[n * NF + j] = lo + hi;
    }
    __syncthreads();

    for (int r = w; r < NN; r += 24) {
        float s = 0.f, ss = 0.f;
        #pragma unroll
        for (int c = lane; c < NF; c += 32) {
            float v = h[r * NF + c];
            s += v; ss += v * v;
        }
        #pragma unroll
        for (int o = 16; o; o >>= 1) {
            s  += __shfl_xor_sync(0xffffffffu, s, o);
            ss += __shfl_xor_sync(0xffffffffu, ss, o);
        }
        if (lane == 0) {
            float m_ = s * (1.f / NF);
            mu[r] = m_;
            rs[r] = rsqrtf(ss * (1.f / NF) - m_ * m_ + 1e-5f);
        }
    }
    __syncthreads();

    const float gg = g[j], bv = bb[j];
    if (MEAN) {
        float macc = 0.f;
        for (int n = 0; n < NN; n++) {
            float v = (h[n * NF + j] - mu[n]) * rs[n] * gg + bv;
            macc += fmaxf(v, 0.f);
        }
        OUT[(size_t)b * NF + j] = macc * (1.f / NN);
    } else {
        for (int n = 0; n < NN; n++) {
            float v = (h[n * NF + j] - mu[n]) * rs[n] * gg + bv;
            OUT[((size_t)b * NN + n) * NF + j] = fmaxf(v, 0.f);
        }
    }
}

// ---------------------------------------------------------------------------
// Skinny classifier GEMM: out[m][n] = op(A[m,:]·W[n,:] + bias[n]), M = 16.
// A [16,K] staged in smem; W original [N,K] row-major; warp per output col.
// ---------------------------------------------------------------------------
template<bool RELU>
__global__ __launch_bounds__(256, 1)
void skinny_fc(const float* __restrict__ A, const float* __restrict__ W,
               const float* __restrict__ bias, float* __restrict__ out,
               int N, int K, int ldo)
{
    extern __shared__ float ys[];
    const int tid = threadIdx.x, w = tid >> 5, lane = tid & 31;

    for (int idx = tid; idx < 16 * K; idx += 256) ys[idx] = A[idx];
    __syncthreads();

    int n = blockIdx.x * 8 + w;
    if (n >= N) return;

    float acc[16];
    #pragma unroll
    for (int m = 0; m < 16; m++) acc[m] = 0.f;

    const float* wp = W + (size_t)n * K;
    for (int k0 = 0; k0 < K; k0 += 32) {
        float wv = wp[k0 + lane];
        #pragma unroll
        for (int m = 0; m < 16; m++)
            acc[m] = fmaf(wv, ys[m * K + k0 + lane], acc[m]);
    }
    #pragma unroll
    for (int m = 0; m < 16; m++) {
        float s = acc[m];
        #pragma unroll
        for (int o = 16; o; o >>= 1) s += __shfl_xor_sync(0xffffffffu, s, o);
        if (lane == 0) {
            float v = s + bias[n];
            if (RELU) v = fmaxf(v, 0.f);
            out[(size_t)m * ldo + n] = v;
        }
    }
}

// ---------------------------------------------------------------------------
// Prep kernels
// ---------------------------------------------------------------------------
__global__ void transpose_kernel(const float* __restrict__ in, float* __restrict__ out,
                                 int R, int C, int ldo, int col_off)
{
    __shared__ float t[32][33];
    int bx = blockIdx.x * 32, by = blockIdx.y * 32;
    int x = bx + threadIdx.x;
    for (int i = threadIdx.y; i < 32; i += 8) {
        int y = by + i;
        t[i][threadIdx.x] = (y < R && x < C) ? in[(size_t)y * C + x] : 0.f;
    }
    __syncthreads();
    int ox = by + threadIdx.x;
    for (int i = threadIdx.y; i < 32; i += 8) {
        int oy = bx + i;
        if (oy < C && ox < R) out[(size_t)oy * ldo + col_off + ox] = t[threadIdx.x][i];
    }
}

__global__ void copy_w0_kernel(const float* __restrict__ w0, float* __restrict__ wcomb)
{
    int k = blockIdx.x;
    for (int n = threadIdx.x; n < NF; n += 256)
        wcomb[(size_t)k * NZW + NF + n] = w0[(size_t)k * NF + n];
}

// coalesced partials: c1[d]=Σ_i wq[i,d]·bk[i], c2[e]=Σ_i wk[i,e]·bq[i]
__global__ void cvec_part(const float* __restrict__ wq, const float* __restrict__ wk,
                          const float* __restrict__ bq, const float* __restrict__ bk,
                          float* __restrict__ cpart)
{
    int d = blockIdx.x * 256 + threadIdx.x;   // 0..1535
    int ic = blockIdx.y;                      // 0..7
    const float* W  = (d < NF) ? wq : wk;
    const float* bv = (d < NF) ? bk : bq;
    int dd = (d < NF) ? d : d - NF;
    float s = 0.f;
    int i0 = ic * 96;
    #pragma unroll 4
    for (int i = i0; i < i0 + 96; i++)
        s += W[(size_t)i * NF + dd] * bv[i];
    cpart[(size_t)ic * 2 * NF + d] = s;
}

__global__ void cvec_comb(const float* __restrict__ cpart, float* __restrict__ cv)
{
    int d = blockIdx.x * 256 + threadIdx.x;
    if (d < 2 * NF) {
        float s = 0.f;
        #pragma unroll
        for (int g = 0; g < 8; g++) s += cpart[(size_t)g * 2 * NF + d];
        cv[d] = s;
    }
}

__global__ void c3_kernel(const float* __restrict__ bq, const float* __restrict__ bk,
                          float* __restrict__ cv)
{
    __shared__ float red[8];
    int tid = threadIdx.x;
    float s = 0.f;
    for (int i = tid; i < NF; i += 256) s += bq[i] * bk[i];
    #pragma unroll
    for (int o = 16; o; o >>= 1) s += __shfl_xor_sync(0xffffffffu, s, o);
    if ((tid & 31) == 0) red[tid >> 5] = s;
    __syncthreads();
    if (tid == 0) {
        float t = 0.f;
        #pragma unroll
        for (int i = 0; i < 8; i++) t += red[i];
        cv[2 * NF] = t;
    }
}

__global__ void concat_kernel(const float* __restrict__ a, const float* __restrict__ g2,
                              float* __restrict__ y, int d)
{
    const int i = blockIdx.x;
    for (int jj = threadIdx.x; jj < d; jj += 256) {
        y[(size_t)i * 2 * d + jj]     = a[(size_t)i * d + jj];
        y[(size_t)i * 2 * d + d + jj] = g2[(size_t)i * d + jj];
    }
}

// ---------------------------------------------------------------------------
// Host side
// ---------------------------------------------------------------------------
static inline dim3 gemm_grid(int M, int N) {
    return dim3((N + 127) / 128, (M + 127) / 128);
}

template<int NN>
static void run_graph(const float* x_in, int Bt,
                      const float* wcomb, const float* cv,
                      const float* gcn_w, const float* ln_g, const float* ln_b,
                      float* p_zxw, float* p_xw, float* p_x, float* p_adj,
                      float* out_mean, size_t sm_fused)
{
    const int M = Bt * NN;
    gemm_tf32<<<gemm_grid(M, NZW), 256, GEMM_SMEM>>>(
        x_in, wcomb, p_zxw, M, NZW, NF, NF, NZW, NZW);
    adj_mma<NN><<<Bt, 256>>>(p_zxw, NZW, x_in, NF, cv, p_adj);
    gcn_fused<NN, false><<<Bt, 768, sm_fused>>>(p_adj, p_zxw + NF, NZW, ln_g, ln_b, p_x);
    gemm_tf32<<<gemm_grid(M, NF), 256, GEMM_SMEM>>>(
        p_x, gcn_w + (size_t)NF * NF, p_xw, M, NF, NF, NF, NF, NF);
    gcn_fused<NN, true><<<Bt, 768, sm_fused>>>(p_adj, p_xw, NF, ln_g + NF, ln_b + NF, out_mean);
}

extern "C" void kernel_launch(void* const* d_in, const int* in_sizes, int n_in,
                              void* d_out, int out_size)
{
    const float* feats  = (const float*)d_in[0];
    const float* fglob  = (const float*)d_in[1];
    const float* wq_w   = (const float*)d_in[3];
    const float* wq_b   = (const float*)d_in[4];
    const float* wk_w   = (const float*)d_in[5];
    const float* wk_b   = (const float*)d_in[6];
    const float* gcn_w  = (const float*)d_in[7];
    const float* ln_g   = (const float*)d_in[8];
    const float* ln_b   = (const float*)d_in[9];
    const float* fc1_w  = (const float*)d_in[10];
    const float* fc1_b  = (const float*)d_in[11];
    const float* fc2_w  = (const float*)d_in[12];
    const float* fc2_b  = (const float*)d_in[13];
    float* out = (float*)d_out;

    float *p_zxw, *p_xw, *p_x, *p_adj, *p_mean, *p_mean2, *p_hc;
    float *p_wcomb, *p_wqT, *p_cv, *p_cpart;
    cudaGetSymbolAddress((void**)&p_zxw,  g_zxw);
    cudaGetSymbolAddress((void**)&p_xw,   g_xw);
    cudaGetSymbolAddress((void**)&p_x,    g_x);
    cudaGetSymbolAddress((void**)&p_adj,  g_adj);
    cudaGetSymbolAddress((void**)&p_mean, g_mean);
    cudaGetSymbolAddress((void**)&p_mean2,g_mean2);
    cudaGetSymbolAddress((void**)&p_hc,   g_hc);
    cudaGetSymbolAddress((void**)&p_wcomb,g_wcomb);
    cudaGetSymbolAddress((void**)&p_wqT,  g_wqT);
    cudaGetSymbolAddress((void**)&p_cv,   g_cvec);
    cudaGetSymbolAddress((void**)&p_cpart,g_cpart);

    const size_t sm50 = (size_t)(NN1 * NN1 + 2 * NN1 + NN1 * NF) * 4;
    const size_t sm32 = (size_t)(NN2 * NN2 + 2 * NN2 + NN2 * NF) * 4;
    const size_t smfc1 = 16 * (size_t)NF2 * 4;   // 98304
    const size_t smfc2 = 16 * (size_t)NF  * 4;   // 49152
    cudaFuncSetAttribute(gcn_fused<NN1, false>, cudaFuncAttributeMaxDynamicSharedMemorySize, (int)sm50);
    cudaFuncSetAttribute(gcn_fused<NN1, true >, cudaFuncAttributeMaxDynamicSharedMemorySize, (int)sm50);
    cudaFuncSetAttribute(gcn_fused<NN2, false>, cudaFuncAttributeMaxDynamicSharedMemorySize, (int)sm32);
    cudaFuncSetAttribute(gcn_fused<NN2, true >, cudaFuncAttributeMaxDynamicSharedMemorySize, (int)sm32);
    cudaFuncSetAttribute(gemm_tf32,  cudaFuncAttributeMaxDynamicSharedMemorySize, GEMM_SMEM);
    cudaFuncSetAttribute(gemm_split, cudaFuncAttributeMaxDynamicSharedMemorySize, GEMM_SMEM);
    cudaFuncSetAttribute(skinny_fc<true >, cudaFuncAttributeMaxDynamicSharedMemorySize, (int)smfc1);
    cudaFuncSetAttribute(skinny_fc<false>, cudaFuncAttributeMaxDynamicSharedMemorySize, (int)smfc2);

    // ---- prep ----
    dim3 tb(32, 8);
    transpose_kernel<<<dim3(NF / 32, NF / 32), tb>>>(wq_w, p_wqT, NF, NF, NF, 0);
    gemm_split<<<gemm_grid(NF, NF), 256, GEMM_SMEM>>>(
        p_wqT, wk_w, p_wcomb, NF, NF, NF, NF, NF, NZW);
    copy_w0_kernel<<<NF, 256>>>(gcn_w, p_wcomb);
    cvec_part<<<dim3(6, 8), 256>>>(wq_w, wk_w, wq_b, wk_b, p_cpart);
    cvec_comb<<<6, 256>>>(p_cpart, p_cv);
    c3_kernel<<<1, 256>>>(wq_b, wk_b, p_cv);

    // ---- graph pass 1: [512, 50, 768] -> [512, 768] ----
    run_graph<NN1>(feats, NB1, p_wcomb, p_cv, gcn_w, ln_g, ln_b,
                   p_zxw, p_xw, p_x, p_adj, p_mean, sm50);

    // ---- graph pass 2: [16, 32, 768] -> [16, 768] ----
    run_graph<NN2>(p_mean, NB2, p_wcomb, p_cv, gcn_w, ln_g, ln_b,
                   p_zxw, p_xw, p_x, p_adj, p_mean2, sm32);

    // ---- classifier ----
    float* y_out = out + NB2 * NC;
    concat_kernel<<<NB2, 256>>>(p_mean2, fglob, y_out, NF);
    skinny_fc<true ><<<NF / 8, 256, smfc1>>>(y_out, fc1_w, fc1_b, p_hc, NF, NF2, NF);
    skinny_fc<false><<<NC / 8, 256, smfc2>>>(p_hc, fc2_w, fc2_b, out, NC, NF, NC);
}

// round 7
// speedup vs baseline: 4.5868x; 1.1134x over previous
#include <cuda_runtime.h>
#include <cstdint>

// ---------------------------------------------------------------------------
// Problem constants
// ---------------------------------------------------------------------------
#define NF   768
#define NB1  512
#define NN1  50
#define NB2  16
#define NN2  32
#define M1   (NB1*NN1)    // 25600
#define NC   400
#define NF2  (2*NF)
#define NZW  1536         // combined z|xw width

// ---------------------------------------------------------------------------
// Scratch (device globals)
// ---------------------------------------------------------------------------
__device__ float g_zxw [(size_t)M1 * NZW];    // z | xw, ld=1536
__device__ float g_xw  [(size_t)M1 * NF];
__device__ float g_x   [(size_t)M1 * NF];
__device__ float g_adj [(size_t)NB1 * NN1 * NN1];
__device__ float g_mean[(size_t)NB1 * NF];
__device__ float g_mean2[(size_t)NB2 * NF];
__device__ float g_hc  [(size_t)NB2 * NF];
__device__ float g_wcomb[(size_t)NF * NZW];   // [K=768][N=1536]: A | W0 (tf32-rounded)
__device__ float g_w1t [(size_t)NF * NF];     // W1 [K][N], tf32-rounded
__device__ float g_wqT [(size_t)NF * NF];
__device__ float g_cvec[2 * NF + 1];          // c1 | c2 | c3
__device__ float g_cpart[8 * 2 * NF];

// ---------------------------------------------------------------------------
// helpers
// ---------------------------------------------------------------------------
__device__ __forceinline__ uint32_t smem_to_u32(const void* p) {
    uint32_t a;
    asm("{ .reg .u64 t; cvta.to.shared.u64 t, %1; cvt.u32.u64 %0, t; }"
        : "=r"(a) : "l"(p));
    return a;
}

__device__ __forceinline__ uint32_t f2tf32(float f) {
    uint32_t r;
    asm("cvt.rna.tf32.f32 %0, %1;" : "=r"(r) : "f"(f));
    return r;
}

__device__ __forceinline__ void mma_tf32(float* d, const uint32_t* a, const uint32_t* b) {
    asm volatile(
        "mma.sync.aligned.m16n8k8.row.col.f32.tf32.tf32.f32 "
        "{%0,%1,%2,%3}, {%4,%5,%6,%7}, {%8,%9}, {%0,%1,%2,%3};"
        : "+f"(d[0]), "+f"(d[1]), "+f"(d[2]), "+f"(d[3])
        : "r"(a[0]), "r"(a[1]), "r"(a[2]), "r"(a[3]), "r"(b[0]), "r"(b[1]));
}

__device__ __forceinline__ void cp_async16(uint32_t dst, const void* src) {
    asm volatile("cp.async.cg.shared.global [%0], [%1], 16;"
                 :: "r"(dst), "l"(src) : "memory");
}
#define CP_COMMIT() asm volatile("cp.async.commit_group;" ::: "memory")
#define CP_WAIT0()  asm volatile("cp.async.wait_group 0;" ::: "memory")

__device__ __forceinline__ unsigned long long fma_f32x2(
    unsigned long long a, unsigned long long b, unsigned long long c) {
    unsigned long long d;
    asm("fma.rn.f32x2 %0, %1, %2, %3;" : "=l"(d) : "l"(a), "l"(b), "l"(c));
    return d;
}
__device__ __forceinline__ unsigned long long pack_f32x2(float lo, float hi) {
    unsigned long long p;
    asm("mov.b64 %0, {%1, %2};" : "=l"(p) : "f"(lo), "f"(hi));
    return p;
}
__device__ __forceinline__ void unpack_f32x2(unsigned long long p, float& lo, float& hi) {
    asm("mov.b64 {%0, %1}, %2;" : "=f"(lo), "=f"(hi) : "l"(p));
}

// ---------------------------------------------------------------------------
// Pipelined TF32 GEMM: C = A[M,K] @ B[K,N]; B pre-rounded to tf32.
// 128x128x32 tile, 256 threads. A: reg-prefetch + cvt at STS.
// B: cp.async double-buffered (pure copy). M%128==0, N%128==0, K%32==0.
// ---------------------------------------------------------------------------
#define GEMM_SMEM 74752

__global__ __launch_bounds__(256, 2)
void gemm_tf32(const float* __restrict__ A, const float* __restrict__ B,
               float* __restrict__ C, int M, int N, int K,
               int lda, int ldb, int ldc)
{
    constexpr int BK = 32, AKP = 40, BNP = 132;
    constexpr int ASZ = 128 * AKP, BSZ = BK * BNP;
    extern __shared__ uint32_t smg[];
    uint32_t* Ab = smg;             // [2][ASZ]
    uint32_t* Bb = smg + 2 * ASZ;   // [2][BSZ]
    const uint32_t sbB = smem_to_u32(Bb);

    const int tid  = threadIdx.x;
    const int wid  = tid >> 5, lane = tid & 31;
    const int gid  = lane >> 2, cq = lane & 3;
    const int wm   = (wid >> 2) * 64, wn = (wid & 3) * 32;
    const int row0 = blockIdx.y * 128, col0 = blockIdx.x * 128;
    const int NK   = K / BK;

    // per-thread B staging coordinates (4 slots of 16B)
    int bk[4], bn4[4];
    #pragma unroll
    for (int i = 0; i < 4; i++) {
        int u = tid + i * 256;
        bk[i]  = u >> 5;
        bn4[i] = (u & 31) * 4;
    }

    // prologue: async B(0) into buf0
    #pragma unroll
    for (int i = 0; i < 4; i++)
        cp_async16(sbB + (uint32_t)(bk[i] * BNP + bn4[i]) * 4,
                   B + (size_t)bk[i] * ldb + col0 + bn4[i]);
    CP_COMMIT();

    // prologue: A(0) regs
    float4 rA[4];
    #pragma unroll
    for (int i = 0; i < 4; i++) {
        int u = tid + i * 256, m = u >> 3, kq = u & 7;
        rA[i] = *reinterpret_cast<const float4*>(A + (size_t)(row0 + m) * lda + 4 * kq);
    }

    float acc[4][4][4];
    #pragma unroll
    for (int i = 0; i < 4; i++)
        #pragma unroll
        for (int j = 0; j < 4; j++)
            #pragma unroll
            for (int q = 0; q < 4; q++) acc[i][j][q] = 0.f;

    for (int s = 0; s < NK; s++) {
        const int p = s & 1;
        uint32_t* Ap = Ab + p * ASZ;
        uint32_t* Bp = Bb + p * BSZ;

        // store prefetched A tile (cvt rna, k-permuted)
        #pragma unroll
        for (int i = 0; i < 4; i++) {
            int u = tid + i * 256, m = u >> 3, kq = u & 7;
            int base = m * AKP + 8 * (kq >> 1) + (kq & 1);
            Ap[base + 0] = f2tf32(rA[i].x);
            Ap[base + 2] = f2tf32(rA[i].y);
            Ap[base + 4] = f2tf32(rA[i].z);
            Ap[base + 6] = f2tf32(rA[i].w);
        }
        CP_WAIT0();
        __syncthreads();
        // now safe: all mma(s-1) done, B(s) resident.
        if (s + 1 < NK) {
            const float* Bn = B + (size_t)(s + 1) * BK * ldb + col0;
            #pragma unroll
            for (int i = 0; i < 4; i++)
                cp_async16(sbB + (uint32_t)((p ^ 1) * BSZ + bk[i] * BNP + bn4[i]) * 4,
                           Bn + (size_t)bk[i] * ldb + bn4[i]);
            CP_COMMIT();
            #pragma unroll
            for (int i = 0; i < 4; i++) {
                int u = tid + i * 256, m = u >> 3, kq = u & 7;
                rA[i] = *reinterpret_cast<const float4*>(
                    A + (size_t)(row0 + m) * lda + (s + 1) * BK + 4 * kq);
            }
        }

        #pragma unroll
        for (int st = 0; st < 4; st++) {
            uint32_t af[4][4];
            #pragma unroll
            for (int mt = 0; mt < 4; mt++) {
                int r0 = wm + mt * 16 + gid;
                uint2 t0 = *reinterpret_cast<const uint2*>(&Ap[(r0    ) * AKP + 8 * st + 2 * cq]);
                uint2 t1 = *reinterpret_cast<const uint2*>(&Ap[(r0 + 8) * AKP + 8 * st + 2 * cq]);
                af[mt][0] = t0.x; af[mt][1] = t1.x; af[mt][2] = t0.y; af[mt][3] = t1.y;
            }
            uint32_t bf[4][2];
            #pragma unroll
            for (int nt = 0; nt < 4; nt++) {
                int cn = wn + nt * 8 + gid;
                bf[nt][0] = Bp[(8 * st + cq    ) * BNP + cn];
                bf[nt][1] = Bp[(8 * st + cq + 4) * BNP + cn];
            }
            #pragma unroll
            for (int mt = 0; mt < 4; mt++)
                #pragma unroll
                for (int nt = 0; nt < 4; nt++)
                    mma_tf32(acc[mt][nt], af[mt], bf[nt]);
        }
    }

    #pragma unroll
    for (int mt = 0; mt < 4; mt++) {
        int rlo = row0 + wm + mt * 16 + gid;
        int rhi = rlo + 8;
        #pragma unroll
        for (int nt = 0; nt < 4; nt++) {
            int cc = col0 + wn + nt * 8 + 2 * cq;
            C[(size_t)rlo * ldc + cc    ] = acc[mt][nt][0];
            C[(size_t)rlo * ldc + cc + 1] = acc[mt][nt][1];
            C[(size_t)rhi * ldc + cc    ] = acc[mt][nt][2];
            C[(size_t)rhi * ldc + cc + 1] = acc[mt][nt][3];
        }
    }
}

// ---------------------------------------------------------------------------
// Split-tf32 GEMM (fp32-accurate) — prep only (A = wq^T @ wk).
// Output rounded to tf32 (it feeds the tf32 GEMM's B operand).
// ---------------------------------------------------------------------------
__global__ __launch_bounds__(256, 1)
void gemm_split(const float* __restrict__ A, const float* __restrict__ B,
                float* __restrict__ C, int M, int N, int K,
                int lda, int ldb, int ldc)
{
    constexpr int BK = 32, AKP = 40, BNP = 132;
    constexpr int ASZ = 128 * AKP, BSZ = BK * BNP;
    extern __shared__ uint32_t smg[];
    uint32_t* Ah = smg;
    uint32_t* Al = smg + ASZ;
    uint32_t* Bh = smg + 2 * ASZ;
    uint32_t* Bl = smg + 2 * ASZ + BSZ;

    const int tid  = threadIdx.x;
    const int wid  = tid >> 5, lane = tid & 31;
    const int gid  = lane >> 2, cq = lane & 3;
    const int wm   = (wid >> 2) * 64, wn = (wid & 3) * 32;
    const int row0 = blockIdx.y * 128, col0 = blockIdx.x * 128;

    float acc[4][4][4];
    #pragma unroll
    for (int i = 0; i < 4; i++)
        #pragma unroll
        for (int j = 0; j < 4; j++)
            #pragma unroll
            for (int q = 0; q < 4; q++) acc[i][j][q] = 0.f;

    for (int k0 = 0; k0 < K; k0 += BK) {
        __syncthreads();
        #pragma unroll
        for (int i = 0; i < 4; i++) {
            int u = tid + i * 256, m = u >> 3, kq = u & 7;
            int gm = row0 + m;
            float4 v = (gm < M) ? *reinterpret_cast<const float4*>(A + (size_t)gm * lda + k0 + 4 * kq)
                                : make_float4(0.f, 0.f, 0.f, 0.f);
            int base = m * AKP + 8 * (kq >> 1) + (kq & 1);
            float xs[4] = {v.x, v.y, v.z, v.w};
            #pragma unroll
            for (int j = 0; j < 4; j++) {
                uint32_t hi = f2tf32(xs[j]);
                Ah[base + 2 * j] = hi;
                Al[base + 2 * j] = f2tf32(xs[j] - __uint_as_float(hi));
            }
        }
        #pragma unroll
        for (int i = 0; i < 4; i++) {
            int u = tid + i * 256, k = u >> 5, nq = u & 31;
            int gn = col0 + 4 * nq;
            const float* bp = B + (size_t)(k0 + k) * ldb + gn;
            int base = k * BNP + 4 * nq;
            #pragma unroll
            for (int j = 0; j < 4; j++) {
                float x = (gn + j < N) ? bp[j] : 0.f;
                uint32_t hi = f2tf32(x);
                Bh[base + j] = hi;
                Bl[base + j] = f2tf32(x - __uint_as_float(hi));
            }
        }
        __syncthreads();

        #pragma unroll
        for (int s = 0; s < 4; s++) {
            uint32_t ah[4][4], al[4][4];
            #pragma unroll
            for (int mt = 0; mt < 4; mt++) {
                int r0 = wm + mt * 16 + gid;
                uint2 t0 = *reinterpret_cast<const uint2*>(&Ah[(r0    ) * AKP + 8 * s + 2 * cq]);
                uint2 t1 = *reinterpret_cast<const uint2*>(&Ah[(r0 + 8) * AKP + 8 * s + 2 * cq]);
                ah[mt][0] = t0.x; ah[mt][1] = t1.x; ah[mt][2] = t0.y; ah[mt][3] = t1.y;
                uint2 u0 = *reinterpret_cast<const uint2*>(&Al[(r0    ) * AKP + 8 * s + 2 * cq]);
                uint2 u1 = *reinterpret_cast<const uint2*>(&Al[(r0 + 8) * AKP + 8 * s + 2 * cq]);
                al[mt][0] = u0.x; al[mt][1] = u1.x; al[mt][2] = u0.y; al[mt][3] = u1.y;
            }
            uint32_t bh[4][2], bl[4][2];
            #pragma unroll
            for (int nt = 0; nt < 4; nt++) {
                int cn = wn + nt * 8 + gid;
                bh[nt][0] = Bh[(8 * s + cq    ) * BNP + cn];
                bh[nt][1] = Bh[(8 * s + cq + 4) * BNP + cn];
                bl[nt][0] = Bl[(8 * s + cq    ) * BNP + cn];
                bl[nt][1] = Bl[(8 * s + cq + 4) * BNP + cn];
            }
            #pragma unroll
            for (int mt = 0; mt < 4; mt++)
                #pragma unroll
                for (int nt = 0; nt < 4; nt++) {
                    mma_tf32(acc[mt][nt], ah[mt], bh[nt]);
                    mma_tf32(acc[mt][nt], ah[mt], bl[nt]);
                    mma_tf32(acc[mt][nt], al[mt], bh[nt]);
                }
        }
    }

    #pragma unroll
    for (int mt = 0; mt < 4; mt++) {
        int rlo = row0 + wm + mt * 16 + gid;
        int rhi = rlo + 8;
        #pragma unroll
        for (int nt = 0; nt < 4; nt++) {
            int cc = col0 + wn + nt * 8 + 2 * cq;
            if (rlo < M) {
                if (cc     < N) C[(size_t)rlo * ldc + cc    ] = __uint_as_float(f2tf32(acc[mt][nt][0]));
                if (cc + 1 < N) C[(size_t)rlo * ldc + cc + 1] = __uint_as_float(f2tf32(acc[mt][nt][1]));
            }
            if (rhi < M) {
                if (cc     < N) C[(size_t)rhi * ldc + cc    ] = __uint_as_float(f2tf32(acc[mt][nt][2]));
                if (cc + 1 < N) C[(size_t)rhi * ldc + cc + 1] = __uint_as_float(f2tf32(acc[mt][nt][3]));
            }
        }
    }
}

// ---------------------------------------------------------------------------
// adj_mma: per batch b, split-tf32 dot = z @ x^T; r1/r2 computed in-kernel.
// adj = dot^2 / max(rowsum(dot^2), 1e-12)
// ---------------------------------------------------------------------------
template<int NN>
__global__ __launch_bounds__(256, 2)
void adj_mma(const float* __restrict__ Z, int ldz,
             const float* __restrict__ X, int ldx,
             const float* __restrict__ cv, float* __restrict__ ADJ)
{
    __shared__ __align__(16) uint32_t sbuf[9728];
    __shared__ float r1s[64], r2s[64];
    uint32_t* qh = sbuf;
    uint32_t* ql = sbuf + 2560;
    uint32_t* kh = sbuf + 5120;
    uint32_t* kl = sbuf + 7424;

    const int b = blockIdx.x, tid = threadIdx.x;
    const int wid = tid >> 5, lane = tid & 31;
    const int gid = lane >> 2, cq = lane & 3;
    const int wm = (wid >> 2) * 32, wn = (wid & 3) * 16;

    const float c3 = cv[2 * NF];
    const int rn = tid >> 2;
    const int rq = tid & 3;

    const float* q = Z + (size_t)b * NN * ldz;
    const float* k = X + (size_t)b * NN * ldx;

    float acc[2][2][4];
    #pragma unroll
    for (int a = 0; a < 2; a++)
        #pragma unroll
        for (int c = 0; c < 2; c++)
            #pragma unroll
            for (int e = 0; e < 4; e++) acc[a][c][e] = 0.f;

    float racc1 = 0.f, racc2 = 0.f;

    for (int k0 = 0; k0 < NF; k0 += 32) {
        __syncthreads();
        #pragma unroll
        for (int i = 0; i < 2; i++) {
            int u = tid + i * 256;
            int m = u >> 3, kq = u & 7;
            float4 v = make_float4(0.f, 0.f, 0.f, 0.f);
            if (m < NN) v = *reinterpret_cast<const float4*>(q + (size_t)m * ldz + k0 + 4 * kq);
            int base = m * 40 + 8 * (kq >> 1) + (kq & 1);
            float xs[4] = {v.x, v.y, v.z, v.w};
            #pragma unroll
            for (int j = 0; j < 4; j++) {
                uint32_t hi = f2tf32(xs[j]);
                qh[base + 2 * j] = hi;
                ql[base + 2 * j] = f2tf32(xs[j] - __uint_as_float(hi));
            }
        }
        #pragma unroll
        for (int i = 0; i < 2; i++) {
            int u = tid + i * 256;
            int n = u >> 3, kq = u & 7;
            float4 v = make_float4(0.f, 0.f, 0.f, 0.f);
            if (n < NN) v = *reinterpret_cast<const float4*>(k + (size_t)n * ldx + k0 + 4 * kq);
            int base = n * 36 + 4 * kq;
            float xs[4] = {v.x, v.y, v.z, v.w};
            #pragma unroll
            for (int j = 0; j < 4; j++) {
                uint32_t hi = f2tf32(xs[j]);
                kh[base + j] = hi;
                kl[base + j] = f2tf32(xs[j] - __uint_as_float(hi));
            }
        }
        __syncthreads();

        {
            const uint32_t* khp = &kh[rn * 36 + rq * 8];
            const uint32_t* klp = &kl[rn * 36 + rq * 8];
            const float* c1p = cv + k0 + rq * 8;
            const float* c2p = cv + NF + k0 + rq * 8;
            #pragma unroll
            for (int kk = 0; kk < 8; kk++) {
                float xm = __uint_as_float(khp[kk]) + __uint_as_float(klp[kk]);
                racc1 += xm * c1p[kk];
                racc2 += xm * c2p[kk];
            }
        }

        #pragma unroll
        for (int s = 0; s < 4; s++) {
            uint32_t ah[2][4], al[2][4], bh[2][2], bl[2][2];
            #pragma unroll
            for (int mt = 0; mt < 2; mt++) {
                int r0 = wm + mt * 16 + gid;
                uint2 t0 = *reinterpret_cast<const uint2*>(&qh[(r0    ) * 40 + 8 * s + 2 * cq]);
                uint2 t1 = *reinterpret_cast<const uint2*>(&qh[(r0 + 8) * 40 + 8 * s + 2 * cq]);
                ah[mt][0] = t0.x; ah[mt][1] = t1.x; ah[mt][2] = t0.y; ah[mt][3] = t1.y;
                uint2 u0 = *reinterpret_cast<const uint2*>(&ql[(r0    ) * 40 + 8 * s + 2 * cq]);
                uint2 u1 = *reinterpret_cast<const uint2*>(&ql[(r0 + 8) * 40 + 8 * s + 2 * cq]);
                al[mt][0] = u0.x; al[mt][1] = u1.x; al[mt][2] = u0.y; al[mt][3] = u1.y;
            }
            #pragma unroll
            for (int nt = 0; nt < 2; nt++) {
                int n = wn + 8 * nt + gid;
                bh[nt][0] = kh[n * 36 + 8 * s + cq];
                bh[nt][1] = kh[n * 36 + 8 * s + cq + 4];
                bl[nt][0] = kl[n * 36 + 8 * s + cq];
                bl[nt][1] = kl[n * 36 + 8 * s + cq + 4];
            }
            #pragma unroll
            for (int mt = 0; mt < 2; mt++)
                #pragma unroll
                for (int nt = 0; nt < 2; nt++) {
                    mma_tf32(acc[mt][nt], ah[mt], bh[nt]);
                    mma_tf32(acc[mt][nt], ah[mt], bl[nt]);
                    mma_tf32(acc[mt][nt], al[mt], bh[nt]);
                }
        }
    }

    #pragma unroll
    for (int o = 1; o <= 2; o <<= 1) {
        racc1 += __shfl_xor_sync(0xffffffffu, racc1, o);
        racc2 += __shfl_xor_sync(0xffffffffu, racc2, o);
    }
    if (rq == 0) { r1s[rn] = racc1; r2s[rn] = racc2; }
    __syncthreads();

    float* sq   = reinterpret_cast<float*>(sbuf);
    float* rinv = reinterpret_cast<float*>(sbuf) + 4400;

    #pragma unroll
    for (int mt = 0; mt < 2; mt++)
        #pragma unroll
        for (int nt = 0; nt < 2; nt++) {
            int r = wm + 16 * mt + gid;
            int c = wn + 8 * nt + 2 * cq;
            float d0 = acc[mt][nt][0] + r1s[r    ] + r2s[c    ] + c3;
            float d1 = acc[mt][nt][1] + r1s[r    ] + r2s[c + 1] + c3;
            float d2 = acc[mt][nt][2] + r1s[r + 8] + r2s[c    ] + c3;
            float d3 = acc[mt][nt][3] + r1s[r + 8] + r2s[c + 1] + c3;
            sq[(r    ) * 68 + c    ] = (c     < NN) ? d0 * d0 : 0.f;
            sq[(r    ) * 68 + c + 1] = (c + 1 < NN) ? d1 * d1 : 0.f;
            sq[(r + 8) * 68 + c    ] = (c     < NN) ? d2 * d2 : 0.f;
            sq[(r + 8) * 68 + c + 1] = (c + 1 < NN) ? d3 * d3 : 0.f;
        }
    __syncthreads();

    for (int r = wid; r < NN; r += 8) {
        float s = sq[r * 68 + lane] + sq[r * 68 + 32 + lane];
        #pragma unroll
        for (int o = 16; o; o >>= 1) s += __shfl_xor_sync(0xffffffffu, s, o);
        if (lane == 0) rinv[r] = 1.f / fmaxf(s, 1e-12f);
    }
    __syncthreads();

    for (int idx = tid; idx < NN * NN; idx += 256) {
        int n = idx / NN, m = idx - n * NN;
        ADJ[(size_t)b * NN * NN + idx] = sq[n * 68 + m] * rinv[n];
    }
}

// ---------------------------------------------------------------------------
// Fused GCN layer with packed f32x2 FMA over node-pairs.
// ---------------------------------------------------------------------------
template<int NN, bool MEAN>
__global__ __launch_bounds__(768, 1)
void gcn_fused(const float* __restrict__ ADJ, const float* __restrict__ XW, int ldxw,
               const float* __restrict__ g, const float* __restrict__ bb,
               float* __restrict__ OUT)
{
    constexpr int NP = NN / 2;
    extern __shared__ float sm[];
    float* adjs = sm;
    float* mu   = sm + NN * NN;
    float* rs   = mu + NN;
    float* h    = rs + NN;

    const int b = blockIdx.x;
    const int j = threadIdx.x;
    const int w = j >> 5, lane = j & 31;

    unsigned long long xc2[NP];
    #pragma unroll
    for (int mi = 0; mi < NP; mi++) {
        float x0 = XW[((size_t)b * NN + 2 * mi    ) * ldxw + j];
        float x1 = XW[((size_t)b * NN + 2 * mi + 1) * ldxw + j];
        xc2[mi] = pack_f32x2(x0, x1);
    }

    for (int idx = j; idx < NN * NN; idx += 768)
        adjs[idx] = ADJ[(size_t)b * NN * NN + idx];
    __syncthreads();

    for (int n = 0; n < NN; n++) {
        const unsigned long long* arow =
            reinterpret_cast<const unsigned long long*>(&adjs[n * NN]);
        unsigned long long a2 = 0ull;
        #pragma unroll
        for (int mi = 0; mi < NP; mi++)
            a2 = fma_f32x2(arow[mi], xc2[mi], a2);
        float lo, hi;
        unpack_f32x2(a2, lo, hi);
        h[n * NF + j] = lo + hi;
    }
    __syncthreads();

    for (int r = w; r < NN; r += 24) {
        float s = 0.f, ss = 0.f;
        #pragma unroll
        for (int c = lane; c < NF; c += 32) {
            float v = h[r * NF + c];
            s += v; ss += v * v;
        }
        #pragma unroll
        for (int o = 16; o; o >>= 1) {
            s  += __shfl_xor_sync(0xffffffffu, s, o);
            ss += __shfl_xor_sync(0xffffffffu, ss, o);
        }
        if (lane == 0) {
            float m_ = s * (1.f / NF);
            mu[r] = m_;
            rs[r] = rsqrtf(ss * (1.f / NF) - m_ * m_ + 1e-5f);
        }
    }
    __syncthreads();

    const float gg = g[j], bv = bb[j];
    if (MEAN) {
        float macc = 0.f;
        for (int n = 0; n < NN; n++) {
            float v = (h[n * NF + j] - mu[n]) * rs[n] * gg + bv;
            macc += fmaxf(v, 0.f);
        }
        OUT[(size_t)b * NF + j] = macc * (1.f / NN);
    } else {
        for (int n = 0; n < NN; n++) {
            float v = (h[n * NF + j] - mu[n]) * rs[n] * gg + bv;
            OUT[((size_t)b * NN + n) * NF + j] = fmaxf(v, 0.f);
        }
    }
}

// ---------------------------------------------------------------------------
// Skinny classifier GEMM (M=16), W original [N][K] row-major.
// ---------------------------------------------------------------------------
template<bool RELU>
__global__ __launch_bounds__(256, 1)
void skinny_fc(const float* __restrict__ A, const float* __restrict__ W,
               const float* __restrict__ bias, float* __restrict__ out,
               int N, int K, int ldo)
{
    extern __shared__ float ys[];
    const int tid = threadIdx.x, w = tid >> 5, lane = tid & 31;

    for (int idx = tid; idx < 16 * K; idx += 256) ys[idx] = A[idx];
    __syncthreads();

    int n = blockIdx.x * 8 + w;
    if (n >= N) return;

    float acc[16];
    #pragma unroll
    for (int m = 0; m < 16; m++) acc[m] = 0.f;

    const float* wp = W + (size_t)n * K;
    for (int k0 = 0; k0 < K; k0 += 32) {
        float wv = wp[k0 + lane];
        #pragma unroll
        for (int m = 0; m < 16; m++)
            acc[m] = fmaf(wv, ys[m * K + k0 + lane], acc[m]);
    }
    #pragma unroll
    for (int m = 0; m < 16; m++) {
        float s = acc[m];
        #pragma unroll
        for (int o = 16; o; o >>= 1) s += __shfl_xor_sync(0xffffffffu, s, o);
        if (lane == 0) {
            float v = s + bias[n];
            if (RELU) v = fmaxf(v, 0.f);
            out[(size_t)m * ldo + n] = v;
        }
    }
}

// ---------------------------------------------------------------------------
// Prep kernels
// ---------------------------------------------------------------------------
__global__ void transpose_kernel(const float* __restrict__ in, float* __restrict__ out,
                                 int R, int C, int ldo, int col_off)
{
    __shared__ float t[32][33];
    int bx = blockIdx.x * 32, by = blockIdx.y * 32;
    int x = bx + threadIdx.x;
    for (int i = threadIdx.y; i < 32; i += 8) {
        int y = by + i;
        t[i][threadIdx.x] = (y < R && x < C) ? in[(size_t)y * C + x] : 0.f;
    }
    __syncthreads();
    int ox = by + threadIdx.x;
    for (int i = threadIdx.y; i < 32; i += 8) {
        int oy = bx + i;
        if (oy < C && ox < R) out[(size_t)oy * ldo + col_off + ox] = t[threadIdx.x][i];
    }
}

// copy W0 into wcomb cols [768..1536), tf32-rounded
__global__ void copy_w0_kernel(const float* __restrict__ w0, float* __restrict__ wcomb)
{
    int k = blockIdx.x;
    for (int n = threadIdx.x; n < NF; n += 256)
        wcomb[(size_t)k * NZW + NF + n] = __uint_as_float(f2tf32(w0[(size_t)k * NF + n]));
}

// tf32-rounded copy (for W1)
__global__ void trunc_copy_kernel(const float* __restrict__ in, float* __restrict__ out, int n)
{
    int i = blockIdx.x * 256 + threadIdx.x;
    if (i < n) out[i] = __uint_as_float(f2tf32(in[i]));
}

__global__ void cvec_part(const float* __restrict__ wq, const float* __restrict__ wk,
                          const float* __restrict__ bq, const float* __restrict__ bk,
                          float* __restrict__ cpart)
{
    int d = blockIdx.x * 256 + threadIdx.x;
    int ic = blockIdx.y;
    const float* W  = (d < NF) ? wq : wk;
    const float* bv = (d < NF) ? bk : bq;
    int dd = (d < NF) ? d : d - NF;
    float s = 0.f;
    int i0 = ic * 96;
    #pragma unroll 4
    for (int i = i0; i < i0 + 96; i++)
        s += W[(size_t)i * NF + dd] * bv[i];
    cpart[(size_t)ic * 2 * NF + d] = s;
}

__global__ void cvec_comb(const float* __restrict__ cpart, float* __restrict__ cv)
{
    int d = blockIdx.x * 256 + threadIdx.x;
    if (d < 2 * NF) {
        float s = 0.f;
        #pragma unroll
        for (int g = 0; g < 8; g++) s += cpart[(size_t)g * 2 * NF + d];
        cv[d] = s;
    }
}

__global__ void c3_kernel(const float* __restrict__ bq, const float* __restrict__ bk,
                          float* __restrict__ cv)
{
    __shared__ float red[8];
    int tid = threadIdx.x;
    float s = 0.f;
    for (int i = tid; i < NF; i += 256) s += bq[i] * bk[i];
    #pragma unroll
    for (int o = 16; o; o >>= 1) s += __shfl_xor_sync(0xffffffffu, s, o);
    if ((tid & 31) == 0) red[tid >> 5] = s;
    __syncthreads();
    if (tid == 0) {
        float t = 0.f;
        #pragma unroll
        for (int i = 0; i < 8; i++) t += red[i];
        cv[2 * NF] = t;
    }
}

__global__ void concat_kernel(const float* __restrict__ a, const float* __restrict__ g2,
                              float* __restrict__ y, int d)
{
    const int i = blockIdx.x;
    for (int jj = threadIdx.x; jj < d; jj += 256) {
        y[(size_t)i * 2 * d + jj]     = a[(size_t)i * d + jj];
        y[(size_t)i * 2 * d + d + jj] = g2[(size_t)i * d + jj];
    }
}

// ---------------------------------------------------------------------------
// Host side
// ---------------------------------------------------------------------------
static inline dim3 gemm_grid(int M, int N) {
    return dim3((N + 127) / 128, (M + 127) / 128);
}

template<int NN>
static void run_graph(const float* x_in, int Bt,
                      const float* wcomb, const float* w1t, const float* cv,
                      const float* ln_g, const float* ln_b,
                      float* p_zxw, float* p_xw, float* p_x, float* p_adj,
                      float* out_mean, size_t sm_fused)
{
    const int M = Bt * NN;
    gemm_tf32<<<gemm_grid(M, NZW), 256, GEMM_SMEM>>>(
        x_in, wcomb, p_zxw, M, NZW, NF, NF, NZW, NZW);
    adj_mma<NN><<<Bt, 256>>>(p_zxw, NZW, x_in, NF, cv, p_adj);
    gcn_fused<NN, false><<<Bt, 768, sm_fused>>>(p_adj, p_zxw + NF, NZW, ln_g, ln_b, p_x);
    gemm_tf32<<<gemm_grid(M, NF), 256, GEMM_SMEM>>>(
        p_x, w1t, p_xw, M, NF, NF, NF, NF, NF);
    gcn_fused<NN, true><<<Bt, 768, sm_fused>>>(p_adj, p_xw, NF, ln_g + NF, ln_b + NF, out_mean);
}

extern "C" void kernel_launch(void* const* d_in, const int* in_sizes, int n_in,
                              void* d_out, int out_size)
{
    const float* feats  = (const float*)d_in[0];
    const float* fglob  = (const float*)d_in[1];
    const float* wq_w   = (const float*)d_in[3];
    const float* wq_b   = (const float*)d_in[4];
    const float* wk_w   = (const float*)d_in[5];
    const float* wk_b   = (const float*)d_in[6];
    const float* gcn_w  = (const float*)d_in[7];
    const float* ln_g   = (const float*)d_in[8];
    const float* ln_b   = (const float*)d_in[9];
    const float* fc1_w  = (const float*)d_in[10];
    const float* fc1_b  = (const float*)d_in[11];
    const float* fc2_w  = (const float*)d_in[12];
    const float* fc2_b  = (const float*)d_in[13];
    float* out = (float*)d_out;

    float *p_zxw, *p_xw, *p_x, *p_adj, *p_mean, *p_mean2, *p_hc;
    float *p_wcomb, *p_w1t, *p_wqT, *p_cv, *p_cpart;
    cudaGetSymbolAddress((void**)&p_zxw,  g_zxw);
    cudaGetSymbolAddress((void**)&p_xw,   g_xw);
    cudaGetSymbolAddress((void**)&p_x,    g_x);
    cudaGetSymbolAddress((void**)&p_adj,  g_adj);
    cudaGetSymbolAddress((void**)&p_mean, g_mean);
    cudaGetSymbolAddress((void**)&p_mean2,g_mean2);
    cudaGetSymbolAddress((void**)&p_hc,   g_hc);
    cudaGetSymbolAddress((void**)&p_wcomb,g_wcomb);
    cudaGetSymbolAddress((void**)&p_w1t,  g_w1t);
    cudaGetSymbolAddress((void**)&p_wqT,  g_wqT);
    cudaGetSymbolAddress((void**)&p_cv,   g_cvec);
    cudaGetSymbolAddress((void**)&p_cpart,g_cpart);

    const size_t sm50 = (size_t)(NN1 * NN1 + 2 * NN1 + NN1 * NF) * 4;
    const size_t sm32 = (size_t)(NN2 * NN2 + 2 * NN2 + NN2 * NF) * 4;
    const size_t smfc1 = 16 * (size_t)NF2 * 4;
    const size_t smfc2 = 16 * (size_t)NF  * 4;
    cudaFuncSetAttribute(gcn_fused<NN1, false>, cudaFuncAttributeMaxDynamicSharedMemorySize, (int)sm50);
    cudaFuncSetAttribute(gcn_fused<NN1, true >, cudaFuncAttributeMaxDynamicSharedMemorySize, (int)sm50);
    cudaFuncSetAttribute(gcn_fused<NN2, false>, cudaFuncAttributeMaxDynamicSharedMemorySize, (int)sm32);
    cudaFuncSetAttribute(gcn_fused<NN2, true >, cudaFuncAttributeMaxDynamicSharedMemorySize, (int)sm32);
    cudaFuncSetAttribute(gemm_tf32,  cudaFuncAttributeMaxDynamicSharedMemorySize, GEMM_SMEM);
    cudaFuncSetAttribute(gemm_split, cudaFuncAttributeMaxDynamicSharedMemorySize, GEMM_SMEM);
    cudaFuncSetAttribute(skinny_fc<true >, cudaFuncAttributeMaxDynamicSharedMemorySize, (int)smfc1);
    cudaFuncSetAttribute(skinny_fc<false>, cudaFuncAttributeMaxDynamicSharedMemorySize, (int)smfc2);

    // ---- prep: wcomb = [A | W0] as [768][1536] (tf32-rounded), W1 rounded copy ----
    dim3 tb(32, 8);
    transpose_kernel<<<dim3(NF / 32, NF / 32), tb>>>(wq_w, p_wqT, NF, NF, NF, 0);
    // A = wq^T @ wk  (cols 0..767 of wcomb), output tf32-rounded
    gemm_split<<<gemm_grid(NF, NF), 256, GEMM_SMEM>>>(
        p_wqT, wk_w, p_wcomb, NF, NF, NF, NF, NF, NZW);
    copy_w0_kernel<<<NF, 256>>>(gcn_w, p_wcomb);
    trunc_copy_kernel<<<(NF * NF + 255) / 256, 256>>>(gcn_w + (size_t)NF * NF, p_w1t, NF * NF);
    cvec_part<<<dim3(6, 8), 256>>>(wq_w, wk_w, wq_b, wk_b, p_cpart);
    cvec_comb<<<6, 256>>>(p_cpart, p_cv);
    c3_kernel<<<1, 256>>>(wq_b, wk_b, p_cv);

    // ---- graph pass 1: [512, 50, 768] -> [512, 768] ----
    run_graph<NN1>(feats, NB1, p_wcomb, p_w1t, p_cv, ln_g, ln_b,
                   p_zxw, p_xw, p_x, p_adj, p_mean, sm50);

    // ---- graph pass 2: [16, 32, 768] -> [16, 768] ----
    run_graph<NN2>(p_mean, NB2, p_wcomb, p_w1t, p_cv, ln_g, ln_b,
                   p_zxw, p_xw, p_x, p_adj, p_mean2, sm32);

    // ---- classifier ----
    float* y_out = out + NB2 * NC;
    concat_kernel<<<NB2, 256>>>(p_mean2, fglob, y_out, NF);
    skinny_fc<true ><<<NF / 8, 256, smfc1>>>(y_out, fc1_w, fc1_b, p_hc, NF, NF2, NF);
    skinny_fc<false><<<NC / 8, 256, smfc2>>>(p_hc, fc2_w, fc2_b, out, NC, NF, NC);
}